// round 14
// baseline (speedup 1.0000x reference)
#include <cuda_runtime.h>
#include <cuda_fp16.h>
#include <cstdint>

#define BATCH 256
#define HDIM  1024
#define EDIM  512
#define SDIM  128
#define VDIM  50257
#define NSCORE (SDIM * BATCH)
#define NB2 ((VDIM + 255) / 256)  // 197 out2 n-blocks

// ---------------- scratch (no allocations allowed) ----------------
__device__ float g_Wh[BATCH * HDIM];
__device__ float g_score4[4 * NSCORE];  // per-nblock score partials
__device__ float g_ctx[BATCH * HDIM];
__device__ float g_g[BATCH * EDIM];
__device__ float g_gates[BATCH * 2 * HDIM];
__device__ float g_t1[BATCH * HDIM];
__device__ float g_t2[BATCH * HDIM];
__device__ __half g_o1h[BATCH * HDIM];         // o1 as fp16
__device__ uint32_t g_UwP[(HDIM / 2) * HDIM];  // U_w k-pair packed fp16
__device__ float g_lmax[NB2 * BATCH];          // out2 per-block row max
__device__ float g_lsum[NB2 * BATCH];          // out2 per-block row sumexp

// ---------------- helpers ----------------
__device__ __forceinline__ float warp_sum(float v) {
#pragma unroll
    for (int o = 16; o > 0; o >>= 1) v += __shfl_xor_sync(0xffffffffu, v, o);
    return v;
}
__device__ __forceinline__ float warp_max(float v) {
#pragma unroll
    for (int o = 16; o > 0; o >>= 1) v = fmaxf(v, __shfl_xor_sync(0xffffffffu, v, o));
    return v;
}

__device__ __forceinline__ void mma8(float* c, const uint32_t* a, const uint32_t* b) {
    asm volatile(
        "mma.sync.aligned.m16n8k8.row.col.f32.tf32.tf32.f32 "
        "{%0,%1,%2,%3}, {%4,%5,%6,%7}, {%8,%9}, {%0,%1,%2,%3};"
        : "+f"(c[0]), "+f"(c[1]), "+f"(c[2]), "+f"(c[3])
        : "r"(a[0]), "r"(a[1]), "r"(a[2]), "r"(a[3]), "r"(b[0]), "r"(b[1]));
}
__device__ __forceinline__ void mma16(float* c, const uint32_t* a, const uint32_t* b) {
    asm volatile(
        "mma.sync.aligned.m16n8k16.row.col.f32.f16.f16.f32 "
        "{%0,%1,%2,%3}, {%4,%5,%6,%7}, {%8,%9}, {%0,%1,%2,%3};"
        : "+f"(c[0]), "+f"(c[1]), "+f"(c[2]), "+f"(c[3])
        : "r"(a[0]), "r"(a[1]), "r"(a[2]), "r"(a[3]), "r"(b[0]), "r"(b[1]));
}

__device__ __forceinline__ void cpa16(void* smem_dst, const void* gsrc) {
    uint32_t d = (uint32_t)__cvta_generic_to_shared(smem_dst);
    asm volatile("cp.async.ca.shared.global [%0], [%1], 16;" ::"r"(d), "l"(gsrc));
}
__device__ __forceinline__ void cpa16z(void* smem_dst, const void* gsrc, int srcsz) {
    uint32_t d = (uint32_t)__cvta_generic_to_shared(smem_dst);
    asm volatile("cp.async.ca.shared.global [%0], [%1], 16, %2;" ::"r"(d), "l"(gsrc),
                 "r"(srcsz));
}
__device__ __forceinline__ void cpa4z(void* smem_dst, const void* gsrc, int srcsz) {
    uint32_t d = (uint32_t)__cvta_generic_to_shared(smem_dst);
    asm volatile("cp.async.ca.shared.global [%0], [%1], 4, %2;" ::"r"(d), "l"(gsrc),
                 "r"(srcsz));
}
__device__ __forceinline__ void cpa_commit() {
    asm volatile("cp.async.commit_group;");
}
__device__ __forceinline__ void cpa_wait1() {
    asm volatile("cp.async.wait_group 1;");
}

__device__ __forceinline__ uint32_t pack_h2(float a, float b) {
    __half2 h = __floats2half2_rn(a, b);
    return *(uint32_t*)&h;
}

// pack B[k][n] fp32 (row stride N) -> BP[k/2][n] u32 (row stride NP)
__global__ void packb_kernel(const float* __restrict__ B, uint32_t* __restrict__ BP,
                             int N, int NP) {
    int n = blockIdx.x * blockDim.x + threadIdx.x;
    int k2 = blockIdx.y;
    if (n < NP) {
        uint32_t out = 0;
        if (n < N)
            out = pack_h2(B[(size_t)(2 * k2) * N + n], B[(size_t)(2 * k2 + 1) * N + n]);
        BP[(size_t)k2 * NP + n] = out;
    }
}

// =====================================================================
// tgemm64: tf32, 64x64 tile, 128 threads (4 warps of 32x32), K-tile 32,
// 3-stage cp.async pipeline. Dynamic smem.
// =====================================================================
#define SM64 ((3 * 64 * 36 + 3 * 32 * 72) * 4)

template <class P>
__launch_bounds__(128)
__global__ void tgemm64(P p) {
    extern __shared__ float dsm64[];
    float(*As)[64][36] = (float(*)[64][36])dsm64;
    float(*Bs)[32][72] = (float(*)[32][72])(dsm64 + 3 * 64 * 36);

    const int tid = threadIdx.x;
    const int lane = tid & 31, wid = tid >> 5;
    const int wm = wid >> 1, wn = wid & 1;
    const int q = lane >> 2, t = lane & 3;
    const int m0 = blockIdx.y * 64;
    const int n0 = blockIdx.x * 64;

    float acc[2][4][4];
#pragma unroll
    for (int i = 0; i < 2; i++)
#pragma unroll
        for (int j = 0; j < 4; j++)
#pragma unroll
            for (int r = 0; r < 4; r++) acc[i][j][r] = 0.0f;

    auto fill = [&](int st, int k0) {
#pragma unroll
        for (int i = 0; i < 4; i++) {
            int c = tid + i * 128;
            int row = c >> 3, kp = (c & 7) << 2;
            cpa16(&As[st][row][kp], p.aChunk(m0 + row, k0 + kp));
        }
        p.copyB(&Bs[st][0][0], n0, k0, tid);
    };

    const int KT = p.K >> 5;
    fill(0, 0);
    cpa_commit();
    fill(1, 32);
    cpa_commit();

    for (int kt = 0; kt < KT; kt++) {
        cpa_wait1();
        __syncthreads();
        if (kt + 2 < KT) fill((kt + 2) % 3, (kt + 2) * 32);
        cpa_commit();
        const int st = kt % 3;

#pragma unroll
        for (int k8 = 0; k8 < 32; k8 += 8) {
            uint32_t af[2][4], bf[4][2];
#pragma unroll
            for (int ni = 0; ni < 4; ni++) {
                int nc = wn * 32 + ni * 8 + q;
                bf[ni][0] = __float_as_uint(Bs[st][k8 + t][nc]);
                bf[ni][1] = __float_as_uint(Bs[st][k8 + t + 4][nc]);
            }
#pragma unroll
            for (int mi = 0; mi < 2; mi++) {
                int mr = wm * 32 + mi * 16 + q;
                af[mi][0] = __float_as_uint(As[st][mr][k8 + t]);
                af[mi][1] = __float_as_uint(As[st][mr + 8][k8 + t]);
                af[mi][2] = __float_as_uint(As[st][mr][k8 + t + 4]);
                af[mi][3] = __float_as_uint(As[st][mr + 8][k8 + t + 4]);
            }
#pragma unroll
            for (int mi = 0; mi < 2; mi++)
#pragma unroll
                for (int ni = 0; ni < 4; ni++) mma8(acc[mi][ni], af[mi], bf[ni]);
        }
    }
    __syncthreads();
    p.store(acc, m0, n0, tid);
}

__device__ __forceinline__ void copyB64_dense(float* bs, const float* B, int ldb,
                                              int n0, int k0, int tid) {
#pragma unroll
    for (int i = 0; i < 4; i++) {
        int c = tid + i * 128;
        int k = c >> 4, np = (c & 15) << 2;
        cpa16(bs + k * 72 + np, B + (size_t)(k0 + k) * ldb + n0 + np);
    }
}

// ---------------- tgemm64 functors ----------------
struct Plain64 {
    const float* A;
    const float* B;
    const float* bias;
    float* C;
    int K;
    int N;
    int act;  // 0=none, 1=relu
    __device__ __forceinline__ const float* aChunk(int r, int k) const {
        return A + (size_t)r * K + k;
    }
    __device__ __forceinline__ void copyB(float* bs, int n0, int k0, int tid) const {
        copyB64_dense(bs, B, N, n0, k0, tid);
    }
    __device__ __forceinline__ void store(const float (&acc)[2][4][4], int m0, int n0,
                                          int tid) const {
        const int lane = tid & 31, wid = tid >> 5, wm = wid >> 1, wn = wid & 1;
#pragma unroll
        for (int mi = 0; mi < 2; mi++) {
            int r = m0 + wm * 32 + mi * 16 + (lane >> 2);
#pragma unroll
            for (int ni = 0; ni < 4; ni++) {
                int c = n0 + wn * 32 + ni * 8 + (lane & 3) * 2;
                float bx = bias[c], by = bias[c + 1];
                float2 lo = make_float2(acc[mi][ni][0] + bx, acc[mi][ni][1] + by);
                float2 hi = make_float2(acc[mi][ni][2] + bx, acc[mi][ni][3] + by);
                if (act == 1) {
                    lo.x = fmaxf(lo.x, 0.f);
                    lo.y = fmaxf(lo.y, 0.f);
                    hi.x = fmaxf(hi.x, 0.f);
                    hi.y = fmaxf(hi.y, 0.f);
                }
                *(float2*)(C + (size_t)r * N + c) = lo;
                *(float2*)(C + (size_t)(r + 8) * N + c) = hi;
            }
        }
    }
};

// relu + fp16 output (o1 -> o1h directly)
struct Plain64H {
    const float* A;
    const float* B;
    const float* bias;
    __half* C;
    int K;
    int N;
    __device__ __forceinline__ const float* aChunk(int r, int k) const {
        return A + (size_t)r * K + k;
    }
    __device__ __forceinline__ void copyB(float* bs, int n0, int k0, int tid) const {
        copyB64_dense(bs, B, N, n0, k0, tid);
    }
    __device__ __forceinline__ void store(const float (&acc)[2][4][4], int m0, int n0,
                                          int tid) const {
        const int lane = tid & 31, wid = tid >> 5, wm = wid >> 1, wn = wid & 1;
#pragma unroll
        for (int mi = 0; mi < 2; mi++) {
            int r = m0 + wm * 32 + mi * 16 + (lane >> 2);
#pragma unroll
            for (int ni = 0; ni < 4; ni++) {
                int c = n0 + wn * 32 + ni * 8 + (lane & 3) * 2;
                float bx = bias[c], by = bias[c + 1];
                __half2 lo = __floats2half2_rn(fmaxf(acc[mi][ni][0] + bx, 0.f),
                                               fmaxf(acc[mi][ni][1] + by, 0.f));
                __half2 hi = __floats2half2_rn(fmaxf(acc[mi][ni][2] + bx, 0.f),
                                               fmaxf(acc[mi][ni][3] + by, 0.f));
                *(__half2*)(C + (size_t)r * N + c) = lo;
                *(__half2*)(C + (size_t)(r + 8) * N + c) = hi;
            }
        }
    }
};

struct Comb64 {
    const float* emb;
    const int* ids;
    const float* ctx;
    const float* B;
    const float* bias;
    float* C;
    int K;
    __device__ __forceinline__ const float* aChunk(int r, int k) const {
        if (k < EDIM) return emb + (size_t)__ldg(&ids[r]) * EDIM + k;
        return ctx + (size_t)r * HDIM + (k - EDIM);
    }
    __device__ __forceinline__ void copyB(float* bs, int n0, int k0, int tid) const {
        copyB64_dense(bs, B, EDIM, n0, k0, tid);
    }
    __device__ __forceinline__ void store(const float (&acc)[2][4][4], int m0, int n0,
                                          int tid) const {
        const int lane = tid & 31, wid = tid >> 5, wm = wid >> 1, wn = wid & 1;
        const int N = EDIM;
#pragma unroll
        for (int mi = 0; mi < 2; mi++) {
            int r = m0 + wm * 32 + mi * 16 + (lane >> 2);
#pragma unroll
            for (int ni = 0; ni < 4; ni++) {
                int c = n0 + wn * 32 + ni * 8 + (lane & 3) * 2;
                float bx = bias[c], by = bias[c + 1];
                float2 lo = make_float2(fmaxf(acc[mi][ni][0] + bx, 0.f),
                                        fmaxf(acc[mi][ni][1] + by, 0.f));
                float2 hi = make_float2(fmaxf(acc[mi][ni][2] + bx, 0.f),
                                        fmaxf(acc[mi][ni][3] + by, 0.f));
                *(float2*)(C + (size_t)r * N + c) = lo;
                *(float2*)(C + (size_t)(r + 8) * N + c) = hi;
            }
        }
    }
};

struct Fused3_64 {
    const float* g;
    const float* hid;
    const float* ihw;
    const float* hhw;
    const float* candw;
    const float* hhcw;
    const float* ihb;
    const float* hhb;
    const float* candb;
    const float* hhcb;
    float* Cg;
    float* Ct1;
    float* Ct2;
    int K;
    __device__ __forceinline__ const float* aChunk(int r, int k) const {
        if (k < EDIM) return g + (size_t)r * EDIM + k;
        return hid + (size_t)r * HDIM + (k - EDIM);
    }
    __device__ __forceinline__ void copyB(float* bs, int n0, int k0, int tid) const {
#pragma unroll
        for (int i = 0; i < 4; i++) {
            int c = tid + i * 128;
            int k = c >> 4, np = (c & 15) << 2;
            int gk = k0 + k, gc = n0 + np;
            const float* src = ihw;
            int sz = 16;
            if (gc < 2048) {
                src = (gk < EDIM) ? ihw + (size_t)gk * 2048 + gc
                                  : hhw + (size_t)(gk - EDIM) * 2048 + gc;
            } else if (gc < 3072) {
                if (gk < EDIM) src = candw + (size_t)gk * HDIM + (gc - 2048);
                else sz = 0;
            } else {
                if (gk >= EDIM) src = hhcw + (size_t)(gk - EDIM) * HDIM + (gc - 3072);
                else sz = 0;
            }
            cpa16z(bs + k * 72 + np, src, sz);
        }
    }
    __device__ __forceinline__ void store(const float (&acc)[2][4][4], int m0, int n0,
                                          int tid) const {
        const int lane = tid & 31, wid = tid >> 5, wm = wid >> 1, wn = wid & 1;
        float* C;
        const float* b0p;
        const float* b1p;
        int N, cbase, sig;
        if (n0 < 2048) {
            C = Cg; N = 2048; cbase = n0; b0p = ihb; b1p = hhb; sig = 1;
        } else if (n0 < 3072) {
            C = Ct1; N = HDIM; cbase = n0 - 2048; b0p = candb; b1p = nullptr; sig = 0;
        } else {
            C = Ct2; N = HDIM; cbase = n0 - 3072; b0p = hhcb; b1p = nullptr; sig = 0;
        }
#pragma unroll
        for (int mi = 0; mi < 2; mi++) {
            int r = m0 + wm * 32 + mi * 16 + (lane >> 2);
#pragma unroll
            for (int ni = 0; ni < 4; ni++) {
                int c = cbase + wn * 32 + ni * 8 + (lane & 3) * 2;
                float bx = b0p[c], by = b0p[c + 1];
                if (b1p) { bx += b1p[c]; by += b1p[c + 1]; }
                float2 lo = make_float2(acc[mi][ni][0] + bx, acc[mi][ni][1] + by);
                float2 hi = make_float2(acc[mi][ni][2] + bx, acc[mi][ni][3] + by);
                if (sig) {
                    lo.x = 1.f / (1.f + expf(-lo.x));
                    lo.y = 1.f / (1.f + expf(-lo.y));
                    hi.x = 1.f / (1.f + expf(-hi.x));
                    hi.y = 1.f / (1.f + expf(-hi.y));
                }
                *(float2*)(C + (size_t)r * N + c) = lo;
                *(float2*)(C + (size_t)(r + 8) * N + c) = hi;
            }
        }
    }
};

// =====================================================================
// score GEMM: fp16 mma, A = RAW fp32 enc staged via cp.async and
// converted to fp16 during fragment load (kills the f2h_enc pass).
// 128x256 tile, 8 warps (64x64), K-tile 32, double-buffered.
//   Af: float[2][128][36]  (rows 144B, 16B-aligned; 2-way frag conflicts OK)
//   Bsm: u32[2][16][264]   (U_w packed fp16 pairs)
// Epilogue: tanh(D + Wh + Ub) . vw -> per-nblock partials.
// =====================================================================
#define AF_ST (128 * 36)
#define BH_ST (16 * 264)
#define SMEMS ((2 * AF_ST + 2 * BH_ST) * 4)

__launch_bounds__(256)
__global__ void score_gemm(const float* __restrict__ enc,
                           const uint32_t* __restrict__ UwP,
                           const float* __restrict__ Wh,
                           const float* __restrict__ Ub,
                           const float* __restrict__ vw,
                           float* __restrict__ part) {
    extern __shared__ uint32_t dsm[];
    float* Af = (float*)dsm;                     // [2][AF_ST]
    uint32_t* Bsm = dsm + 2 * AF_ST;             // [2][BH_ST]

    const int tid = threadIdx.x;
    const int lane = tid & 31, wid = tid >> 5;
    const int wm = wid >> 2, wn = wid & 3;
    const int q = lane >> 2, t = lane & 3;
    const int m0 = blockIdx.y * 128;
    const int n0 = blockIdx.x * 256;

    float acc[4][8][4];
#pragma unroll
    for (int i = 0; i < 4; i++)
#pragma unroll
        for (int j = 0; j < 8; j++)
#pragma unroll
            for (int r = 0; r < 4; r++) acc[i][j][r] = 0.0f;

    auto copyA = [&](int st, int k0) {
        float* ab = Af + st * AF_ST;
#pragma unroll
        for (int i = 0; i < 4; i++) {
            int idx = tid + i * 256;  // 1024 chunks: 128 rows x 8 (4 fp32 each)
            int row = idx >> 3, c4 = (idx & 7);
            cpa16(ab + row * 36 + c4 * 4,
                  enc + (size_t)(m0 + row) * HDIM + k0 + c4 * 4);
        }
    };
    auto copyB = [&](int st, int k0) {
        uint32_t* bb = Bsm + st * BH_ST;
        const int k20 = k0 >> 1;
#pragma unroll
        for (int i = 0; i < 4; i++) {
            int idx = tid + i * 256;  // 1024 chunks: 16 k2-rows x 64 (4 u32 each)
            int k2 = idx >> 6, np = (idx & 63) << 2;
            cpa16(bb + k2 * 264 + np, UwP + (size_t)(k20 + k2) * HDIM + n0 + np);
        }
    };

    const int KT = HDIM >> 5;
    copyA(0, 0);
    copyB(0, 0);
    cpa_commit();
    copyA(1, 32);
    copyB(1, 32);
    cpa_commit();

    for (int kt = 0; kt < KT; kt++) {
        cpa_wait1();
        __syncthreads();
        const int st = kt & 1;
        const float* ab = Af + st * AF_ST;
        const uint32_t* bb = Bsm + st * BH_ST;

#pragma unroll
        for (int g = 0; g < 2; g++) {  // two k16 groups
            const int o = g * 8;       // u32 row base (B)
            const int o2 = g * 16;     // fp32 col base (A)
            uint32_t af[4][4], bf[8][2];
#pragma unroll
            for (int ni = 0; ni < 8; ni++) {
                int nc = wn * 64 + ni * 8 + q;
                bf[ni][0] = bb[(o + t) * 264 + nc];
                bf[ni][1] = bb[(o + t + 4) * 264 + nc];
            }
#pragma unroll
            for (int mi = 0; mi < 4; mi++) {
                int mr = wm * 64 + mi * 16 + q;
                float2 a0 = *(const float2*)&ab[mr * 36 + o2 + 2 * t];
                float2 a1 = *(const float2*)&ab[(mr + 8) * 36 + o2 + 2 * t];
                float2 a2 = *(const float2*)&ab[mr * 36 + o2 + 2 * t + 8];
                float2 a3 = *(const float2*)&ab[(mr + 8) * 36 + o2 + 2 * t + 8];
                af[mi][0] = pack_h2(a0.x, a0.y);
                af[mi][1] = pack_h2(a1.x, a1.y);
                af[mi][2] = pack_h2(a2.x, a2.y);
                af[mi][3] = pack_h2(a3.x, a3.y);
            }
#pragma unroll
            for (int mi = 0; mi < 4; mi++)
#pragma unroll
                for (int ni = 0; ni < 8; ni++) mma16(acc[mi][ni], af[mi], bf[ni]);
        }
        __syncthreads();
        if (kt + 2 < KT) {
            copyA(st, (kt + 2) * 32);
            copyB(st, (kt + 2) * 32);
        }
        cpa_commit();
    }

    // ---- epilogue: tanh(D + Wh + Ub) . vw -> per-row partial ----
    float* red = (float*)dsm;  // 4*128 floats, safe post-loop
    __syncthreads();
#pragma unroll
    for (int mi = 0; mi < 4; mi++) {
        int r0 = m0 + wm * 64 + mi * 16 + q;
        const float* wh0 = Wh + (size_t)(r0 & (BATCH - 1)) * HDIM;
        const float* wh1 = Wh + (size_t)((r0 + 8) & (BATCH - 1)) * HDIM;
        float s0 = 0.f, s1 = 0.f;
#pragma unroll
        for (int ni = 0; ni < 8; ni++) {
            int c = n0 + wn * 64 + ni * 8 + t * 2;
            float u0 = Ub[c], u1 = Ub[c + 1];
            float w0 = vw[c], w1 = vw[c + 1];
            s0 += tanhf(acc[mi][ni][0] + wh0[c] + u0) * w0;
            s0 += tanhf(acc[mi][ni][1] + wh0[c + 1] + u1) * w1;
            s1 += tanhf(acc[mi][ni][2] + wh1[c] + u0) * w0;
            s1 += tanhf(acc[mi][ni][3] + wh1[c + 1] + u1) * w1;
        }
        s0 += __shfl_xor_sync(0xffffffffu, s0, 1);
        s0 += __shfl_xor_sync(0xffffffffu, s0, 2);
        s1 += __shfl_xor_sync(0xffffffffu, s1, 1);
        s1 += __shfl_xor_sync(0xffffffffu, s1, 2);
        if (t == 0) {
            red[wn * 128 + wm * 64 + mi * 16 + q] = s0;
            red[wn * 128 + wm * 64 + mi * 16 + q + 8] = s1;
        }
    }
    __syncthreads();
    if (tid < 128)
        part[(size_t)(n0 >> 8) * NSCORE + m0 + tid] =
            red[tid] + red[128 + tid] + red[256 + tid] + red[384 + tid];
}

// =====================================================================
// out2 GEMM: fp16 mma, B staged as RAW fp32 via 4-BYTE cp.async.
// Epilogue: stores logits AND per-block row max / sumexp partials.
// =====================================================================
#define AH_ST (128 * 20)
#define BO_ST (32 * 260)
#define SMEMO ((2 * AH_ST + 2 * BO_ST) * 4)

__launch_bounds__(256)
__global__ void out2_gemm(const __half* __restrict__ AH,
                          const float* __restrict__ B,
                          const float* __restrict__ bias,
                          float* __restrict__ C,
                          float* __restrict__ lmax,
                          float* __restrict__ lsum) {
    extern __shared__ uint32_t dsm[];
    uint32_t* Asm = dsm;                    // [2][AH_ST]
    float* Bf = (float*)(dsm + 2 * AH_ST);  // [2][BO_ST]

    const int tid = threadIdx.x;
    const int lane = tid & 31, wid = tid >> 5;
    const int wm = wid >> 2, wn = wid & 3;
    const int q = lane >> 2, t = lane & 3;
    const int m0 = blockIdx.x * 128;  // m fastest
    const int n0 = blockIdx.y * 256;
    const int nb = blockIdx.y;

    float acc[4][8][4];
#pragma unroll
    for (int i = 0; i < 4; i++)
#pragma unroll
        for (int j = 0; j < 8; j++)
#pragma unroll
            for (int r = 0; r < 4; r++) acc[i][j][r] = 0.0f;

    auto copyA = [&](int st, int k0) {
        uint32_t* ab = Asm + st * AH_ST;
#pragma unroll
        for (int i = 0; i < 2; i++) {
            int idx = tid + i * 256;
            int row = idx >> 2, c8 = (idx & 3);
            cpa16(ab + row * 20 + c8 * 4, AH + (size_t)(m0 + row) * HDIM + k0 + c8 * 8);
        }
    };
    auto copyB = [&](int st, int k0) {
        float* bb = Bf + st * BO_ST;
#pragma unroll
        for (int i = 0; i < 32; i++) {
            int idx = tid + i * 256;  // 8192 words: 32 k-rows x 256
            int k = idx >> 8, n = idx & 255;
            int gn = n0 + n;
            int ok = gn < VDIM;
            const float* src = B + (size_t)(k0 + k) * VDIM + (ok ? gn : 0);
            cpa4z(bb + k * 260 + n, src, ok ? 4 : 0);
        }
    };

    const int KT = HDIM >> 5;
    copyA(0, 0);
    copyB(0, 0);
    cpa_commit();
    copyA(1, 32);
    copyB(1, 32);
    cpa_commit();

    for (int kt = 0; kt < KT; kt++) {
        cpa_wait1();
        __syncthreads();
        const int st = kt & 1;
        const uint32_t* ab = Asm + st * AH_ST;
        const float* bb = Bf + st * BO_ST;

#pragma unroll
        for (int g = 0; g < 2; g++) {  // two k16 groups
            const int o = g * 16;      // fp32 row base
            uint32_t af[4][4], bf[8][2];
#pragma unroll
            for (int ni = 0; ni < 8; ni++) {
                int nc = wn * 64 + ni * 8 + q;
                bf[ni][0] = pack_h2(bb[(o + 2 * t) * 260 + nc],
                                    bb[(o + 2 * t + 1) * 260 + nc]);
                bf[ni][1] = pack_h2(bb[(o + 2 * t + 8) * 260 + nc],
                                    bb[(o + 2 * t + 9) * 260 + nc]);
            }
#pragma unroll
            for (int mi = 0; mi < 4; mi++) {
                int mr = wm * 64 + mi * 16 + q;
                af[mi][0] = ab[mr * 20 + g * 8 + t];
                af[mi][1] = ab[(mr + 8) * 20 + g * 8 + t];
                af[mi][2] = ab[mr * 20 + g * 8 + t + 4];
                af[mi][3] = ab[(mr + 8) * 20 + g * 8 + t + 4];
            }
#pragma unroll
            for (int mi = 0; mi < 4; mi++)
#pragma unroll
                for (int ni = 0; ni < 8; ni++) mma16(acc[mi][ni], af[mi], bf[ni]);
        }
        __syncthreads();
        if (kt + 2 < KT) {
            copyA(st, (kt + 2) * 32);
            copyB(st, (kt + 2) * 32);
        }
        cpa_commit();
    }

    // ---- epilogue: store logits + block-row max / sumexp ----
    __syncthreads();
    float* redm = (float*)dsm;  // [4][128]
    float* bmax = redm + 512;   // [128]

#pragma unroll
    for (int mi = 0; mi < 4; mi++) {
#pragma unroll
        for (int half = 0; half < 2; half++) {
            int rl = wm * 64 + mi * 16 + q + half * 8;
            int r = m0 + rl;
            float mx = -3.4e38f;
#pragma unroll
            for (int ni = 0; ni < 8; ni++) {
                int c0 = n0 + wn * 64 + ni * 8 + t * 2;
                if (c0 < VDIM) {
                    float v0 = acc[mi][ni][half * 2 + 0] + bias[c0];
                    C[(size_t)r * VDIM + c0] = v0;
                    mx = fmaxf(mx, v0);
                }
                if (c0 + 1 < VDIM) {
                    float v1 = acc[mi][ni][half * 2 + 1] + bias[c0 + 1];
                    C[(size_t)r * VDIM + c0 + 1] = v1;
                    mx = fmaxf(mx, v1);
                }
            }
            mx = fmaxf(mx, __shfl_xor_sync(0xffffffffu, mx, 1));
            mx = fmaxf(mx, __shfl_xor_sync(0xffffffffu, mx, 2));
            if (t == 0) redm[wn * 128 + rl] = mx;
        }
    }
    __syncthreads();
    if (tid < 128)
        bmax[tid] = fmaxf(fmaxf(redm[tid], redm[128 + tid]),
                          fmaxf(redm[256 + tid], redm[384 + tid]));
    __syncthreads();

#pragma unroll
    for (int mi = 0; mi < 4; mi++) {
#pragma unroll
        for (int half = 0; half < 2; half++) {
            int rl = wm * 64 + mi * 16 + q + half * 8;
            float bm = bmax[rl];
            float s = 0.f;
#pragma unroll
            for (int ni = 0; ni < 8; ni++) {
                int c0 = n0 + wn * 64 + ni * 8 + t * 2;
                if (c0 < VDIM) s += expf(acc[mi][ni][half * 2 + 0] + bias[c0] - bm);
                if (c0 + 1 < VDIM)
                    s += expf(acc[mi][ni][half * 2 + 1] + bias[c0 + 1] - bm);
            }
            s += __shfl_xor_sync(0xffffffffu, s, 1);
            s += __shfl_xor_sync(0xffffffffu, s, 2);
            if (t == 0) redm[wn * 128 + rl] = s;
        }
    }
    __syncthreads();
    if (tid < 128) {
        lmax[(size_t)nb * BATCH + m0 + tid] = bmax[tid];
        lsum[(size_t)nb * BATCH + m0 + tid] =
            redm[tid] + redm[128 + tid] + redm[256 + tid] + redm[384 + tid];
    }
}

// ---------------- fused softmax(S) + context (fp32 enc) ----------------
__global__ void softmax_ctx_kernel(const float* __restrict__ part,
                                   const float* __restrict__ enc,
                                   float* __restrict__ attn_out,
                                   float* __restrict__ ctx) {
    const int n = blockIdx.x;
    const int tid = threadIdx.x;  // 256
    __shared__ float a[SDIM];
    __shared__ float rmax[4], rsum[4];

    float v = 0.f, e = 0.f;
    if (tid < SDIM) {
        const int idx = tid * BATCH + n;
        v = part[idx] + part[NSCORE + idx] + part[2 * NSCORE + idx] +
            part[3 * NSCORE + idx];
        float m = warp_max(v);
        if ((tid & 31) == 0) rmax[tid >> 5] = m;
    }
    __syncthreads();
    if (tid < SDIM) {
        float m = fmaxf(fmaxf(rmax[0], rmax[1]), fmaxf(rmax[2], rmax[3]));
        e = expf(v - m);
        float s = warp_sum(e);
        if ((tid & 31) == 0) rsum[tid >> 5] = s;
    }
    __syncthreads();
    if (tid < SDIM) {
        float sum = rsum[0] + rsum[1] + rsum[2] + rsum[3];
        float av = e / sum;
        attn_out[tid * BATCH + n] = av;
        a[tid] = av;
    }
    __syncthreads();

    float4 acc = make_float4(0.f, 0.f, 0.f, 0.f);
    for (int s = 0; s < SDIM; s++) {
        float4 ev = ((const float4*)(enc + ((size_t)s * BATCH + n) * HDIM))[tid];
        float w = a[s];
        acc.x = fmaf(w, ev.x, acc.x);
        acc.y = fmaf(w, ev.y, acc.y);
        acc.z = fmaf(w, ev.z, acc.z);
        acc.w = fmaf(w, ev.w, acc.w);
    }
    ((float4*)(ctx + (size_t)n * HDIM))[tid] = acc;
}

// ---------------- GRU combine + LayerNorm ----------------
__global__ void fuse_hln_kernel(const float* __restrict__ gates,
                                const float* __restrict__ t1,
                                const float* __restrict__ t2,
                                const float* __restrict__ hid,
                                const float* __restrict__ lng,
                                const float* __restrict__ lnb,
                                float* __restrict__ hout) {
    const int n = blockIdx.x;
    const int tid = threadIdx.x;  // 256
    float4 z = ((const float4*)(gates + (size_t)n * 2 * HDIM))[tid];
    float4 r = ((const float4*)(gates + (size_t)n * 2 * HDIM + HDIM))[tid];
    float4 a = ((const float4*)(t1 + (size_t)n * HDIM))[tid];
    float4 b = ((const float4*)(t2 + (size_t)n * HDIM))[tid];
    float4 hv = ((const float4*)(hid + (size_t)n * HDIM))[tid];
    float4 hr;
    hr.x = (1.0f - z.x) * hv.x + z.x * tanhf(a.x + r.x * b.x);
    hr.y = (1.0f - z.y) * hv.y + z.y * tanhf(a.y + r.y * b.y);
    hr.z = (1.0f - z.z) * hv.z + z.z * tanhf(a.z + r.z * b.z);
    hr.w = (1.0f - z.w) * hv.w + z.w * tanhf(a.w + r.w * b.w);
    float s = hr.x + hr.y + hr.z + hr.w;
    float ss = hr.x * hr.x + hr.y * hr.y + hr.z * hr.z + hr.w * hr.w;
    __shared__ float sm1[8], sm2[8];
    float w1 = warp_sum(s), w2 = warp_sum(ss);
    if ((tid & 31) == 0) { sm1[tid >> 5] = w1; sm2[tid >> 5] = w2; }
    __syncthreads();
    float tot1 = 0.f, tot2 = 0.f;
#pragma unroll
    for (int qq = 0; qq < 8; qq++) { tot1 += sm1[qq]; tot2 += sm2[qq]; }
    float mu = tot1 * (1.0f / HDIM);
    float var = tot2 * (1.0f / HDIM) - mu * mu;
    float inv = rsqrtf(var + 1e-5f);
    float4 gg = ((const float4*)lng)[tid];
    float4 bb = ((const float4*)lnb)[tid];
    float4 o;
    o.x = (hr.x - mu) * inv * gg.x + bb.x;
    o.y = (hr.y - mu) * inv * gg.y + bb.y;
    o.z = (hr.z - mu) * inv * gg.z + bb.z;
    o.w = (hr.w - mu) * inv * gg.w + bb.w;
    ((float4*)(hout + (size_t)n * HDIM))[tid] = o;
}

// ---------------- final log_softmax: reduce partials + single RW pass ---------
__global__ void logsoftmax2_kernel(float* __restrict__ logits,
                                   const float* __restrict__ lmax,
                                   const float* __restrict__ lsum) {
    const int n = blockIdx.x;
    const int tid = threadIdx.x;  // 512
    __shared__ float sm[16];

    float m = -3.4e38f;
    for (int i = tid; i < NB2; i += 512) m = fmaxf(m, lmax[(size_t)i * BATCH + n]);
    m = warp_max(m);
    if ((tid & 31) == 0) sm[tid >> 5] = m;
    __syncthreads();
    float gmax = -3.4e38f;
#pragma unroll
    for (int qq = 0; qq < 16; qq++) gmax = fmaxf(gmax, sm[qq]);
    __syncthreads();

    float s = 0.f;
    for (int i = tid; i < NB2; i += 512)
        s += lsum[(size_t)i * BATCH + n] * expf(lmax[(size_t)i * BATCH + n] - gmax);
    s = warp_sum(s);
    if ((tid & 31) == 0) sm[tid >> 5] = s;
    __syncthreads();
    float tot = 0.f;
#pragma unroll
    for (int qq = 0; qq < 16; qq++) tot += sm[qq];
    float lse = gmax + logf(tot);

    float* row = logits + (size_t)n * VDIM;
    for (int i = tid; i < VDIM; i += 512) row[i] -= lse;
}

// ---------------- launch ----------------
extern "C" void kernel_launch(void* const* d_in, const int* in_sizes, int n_in,
                              void* d_out, int out_size) {
    const int* ids = (const int*)d_in[0];
    const float* hidden = (const float*)d_in[1];
    const float* enc = (const float*)d_in[2];
    const float* emb = (const float*)d_in[3];
    const float* W_w = (const float*)d_in[4];
    const float* W_b = (const float*)d_in[5];
    const float* U_w = (const float*)d_in[6];
    const float* U_b = (const float*)d_in[7];
    const float* v_w = (const float*)d_in[8];
    // d_in[9] = v_b : constant over S, cancels in softmax
    const float* ih_w = (const float*)d_in[10];
    const float* ih_b = (const float*)d_in[11];
    const float* hh_w = (const float*)d_in[12];
    const float* hh_b = (const float*)d_in[13];
    const float* cand_w = (const float*)d_in[14];
    const float* cand_b = (const float*)d_in[15];
    const float* hhc_w = (const float*)d_in[16];
    const float* hhc_b = (const float*)d_in[17];
    const float* comb_w = (const float*)d_in[18];
    const float* comb_b = (const float*)d_in[19];
    const float* ln_g = (const float*)d_in[20];
    const float* ln_b = (const float*)d_in[21];
    const float* out1_w = (const float*)d_in[22];
    const float* out1_b = (const float*)d_in[23];
    const float* out2_w = (const float*)d_in[24];
    const float* out2_b = (const float*)d_in[25];

    float* out_logits = (float*)d_out;
    float* out_h = out_logits + (size_t)BATCH * VDIM;
    float* out_attn = out_h + (size_t)BATCH * HDIM;

    float *Wh, *score4, *ctx, *gbuf, *gates, *t1, *t2, *lmax, *lsum;
    __half* o1h;
    uint32_t* UwP;
    cudaGetSymbolAddress((void**)&Wh, g_Wh);
    cudaGetSymbolAddress((void**)&score4, g_score4);
    cudaGetSymbolAddress((void**)&ctx, g_ctx);
    cudaGetSymbolAddress((void**)&gbuf, g_g);
    cudaGetSymbolAddress((void**)&gates, g_gates);
    cudaGetSymbolAddress((void**)&t1, g_t1);
    cudaGetSymbolAddress((void**)&t2, g_t2);
    cudaGetSymbolAddress((void**)&o1h, g_o1h);
    cudaGetSymbolAddress((void**)&UwP, g_UwP);
    cudaGetSymbolAddress((void**)&lmax, g_lmax);
    cudaGetSymbolAddress((void**)&lsum, g_lsum);

    cudaFuncSetAttribute(score_gemm, cudaFuncAttributeMaxDynamicSharedMemorySize,
                         SMEMS);
    cudaFuncSetAttribute(out2_gemm, cudaFuncAttributeMaxDynamicSharedMemorySize,
                         SMEMO);
    cudaFuncSetAttribute(tgemm64<Plain64>,
                         cudaFuncAttributeMaxDynamicSharedMemorySize, SM64);
    cudaFuncSetAttribute(tgemm64<Plain64H>,
                         cudaFuncAttributeMaxDynamicSharedMemorySize, SM64);
    cudaFuncSetAttribute(tgemm64<Comb64>,
                         cudaFuncAttributeMaxDynamicSharedMemorySize, SM64);
    cudaFuncSetAttribute(tgemm64<Fused3_64>,
                         cudaFuncAttributeMaxDynamicSharedMemorySize, SM64);

    // 0. pack U_w only (enc conversion folded into score_gemm)
    packb_kernel<<<dim3(HDIM / 256, HDIM / 2), 256>>>(U_w, UwP, HDIM, HDIM);

    // 1. Wh = hidden @ W_w + W_b
    {
        Plain64 p{hidden, W_w, W_b, Wh, HDIM, HDIM, 0};
        tgemm64<Plain64><<<dim3(HDIM / 64, BATCH / 64), 128, SM64>>>(p);
    }
    // 2. fused score GEMM (fp32 A in-kernel cvt) -> 4 partial buffers
    score_gemm<<<dim3(HDIM / 256, (SDIM * BATCH) / 128), 256, SMEMS>>>(
        enc, UwP, Wh, U_b, v_w, score4);
    // 3. fused softmax + context
    softmax_ctx_kernel<<<BATCH, 256>>>(score4, enc, out_attn, ctx);
    // 4. g = relu([emb[ids], ctx] @ comb_w + comb_b)
    {
        Comb64 p{emb, ids, ctx, comb_w, comb_b, gbuf, EDIM + HDIM};
        tgemm64<Comb64><<<dim3(EDIM / 64, BATCH / 64), 128, SM64>>>(p);
    }
    // 5. fused gates | t1 | t2
    {
        Fused3_64 p{gbuf, hidden, ih_w, hh_w, cand_w, hhc_w,
                    ih_b, hh_b, cand_b, hhc_b, gates, t1, t2, EDIM + HDIM};
        tgemm64<Fused3_64><<<dim3(4096 / 64, BATCH / 64), 128, SM64>>>(p);
    }
    // 6. GRU combine + LayerNorm
    fuse_hln_kernel<<<BATCH, 256>>>(gates, t1, t2, hidden, ln_g, ln_b, out_h);
    // 7. o1h = relu(h @ out1_w + out1_b) directly in fp16
    {
        Plain64H p{out_h, out1_w, out1_b, o1h, HDIM, HDIM};
        tgemm64<Plain64H><<<dim3(HDIM / 64, BATCH / 64), 128, SM64>>>(p);
    }
    // 8. logits + fused log-softmax partials
    out2_gemm<<<dim3(BATCH / 128, NB2), 256, SMEMO>>>(o1h, out2_w, out2_b, out_logits,
                                                      lmax, lsum);
    // 9. final log_softmax: reduce partials + single pass
    logsoftmax2_kernel<<<BATCH, 512>>>(out_logits, lmax, lsum);
}

// round 15
// speedup vs baseline: 1.0884x; 1.0884x over previous
#include <cuda_runtime.h>
#include <cuda_fp16.h>
#include <cstdint>

#define BATCH 256
#define HDIM  1024
#define EDIM  512
#define SDIM  128
#define VDIM  50257
#define NSCORE (SDIM * BATCH)
#define NB2 ((VDIM + 255) / 256)  // 197 out2 n-blocks

// ---------------- scratch (no allocations allowed) ----------------
__device__ float g_Wh[BATCH * HDIM];
__device__ float g_score4[4 * NSCORE];  // per-nblock score partials
__device__ float g_ctx[BATCH * HDIM];
__device__ float g_g[BATCH * EDIM];
__device__ float g_gates[BATCH * 2 * HDIM];
__device__ float g_t1[BATCH * HDIM];
__device__ float g_t2[BATCH * HDIM];
__device__ __half g_encH[SDIM * BATCH * HDIM];  // enc as fp16
__device__ __half g_o1h[BATCH * HDIM];          // o1 as fp16
__device__ uint32_t g_UwP[(HDIM / 2) * HDIM];   // U_w k-pair packed fp16
__device__ float g_lmax[NB2 * BATCH];           // out2 per-block row max
__device__ float g_lsum[NB2 * BATCH];           // out2 per-block row sumexp

// ---------------- helpers ----------------
__device__ __forceinline__ float warp_sum(float v) {
#pragma unroll
    for (int o = 16; o > 0; o >>= 1) v += __shfl_xor_sync(0xffffffffu, v, o);
    return v;
}
__device__ __forceinline__ float warp_max(float v) {
#pragma unroll
    for (int o = 16; o > 0; o >>= 1) v = fmaxf(v, __shfl_xor_sync(0xffffffffu, v, o));
    return v;
}

__device__ __forceinline__ void mma8(float* c, const uint32_t* a, const uint32_t* b) {
    asm volatile(
        "mma.sync.aligned.m16n8k8.row.col.f32.tf32.tf32.f32 "
        "{%0,%1,%2,%3}, {%4,%5,%6,%7}, {%8,%9}, {%0,%1,%2,%3};"
        : "+f"(c[0]), "+f"(c[1]), "+f"(c[2]), "+f"(c[3])
        : "r"(a[0]), "r"(a[1]), "r"(a[2]), "r"(a[3]), "r"(b[0]), "r"(b[1]));
}
__device__ __forceinline__ void mma16(float* c, const uint32_t* a, const uint32_t* b) {
    asm volatile(
        "mma.sync.aligned.m16n8k16.row.col.f32.f16.f16.f32 "
        "{%0,%1,%2,%3}, {%4,%5,%6,%7}, {%8,%9}, {%0,%1,%2,%3};"
        : "+f"(c[0]), "+f"(c[1]), "+f"(c[2]), "+f"(c[3])
        : "r"(a[0]), "r"(a[1]), "r"(a[2]), "r"(a[3]), "r"(b[0]), "r"(b[1]));
}

__device__ __forceinline__ void cpa16(void* smem_dst, const void* gsrc) {
    uint32_t d = (uint32_t)__cvta_generic_to_shared(smem_dst);
    asm volatile("cp.async.ca.shared.global [%0], [%1], 16;" ::"r"(d), "l"(gsrc));
}
__device__ __forceinline__ void cpa16z(void* smem_dst, const void* gsrc, int srcsz) {
    uint32_t d = (uint32_t)__cvta_generic_to_shared(smem_dst);
    asm volatile("cp.async.ca.shared.global [%0], [%1], 16, %2;" ::"r"(d), "l"(gsrc),
                 "r"(srcsz));
}
__device__ __forceinline__ void cpa4z(void* smem_dst, const void* gsrc, int srcsz) {
    uint32_t d = (uint32_t)__cvta_generic_to_shared(smem_dst);
    asm volatile("cp.async.ca.shared.global [%0], [%1], 4, %2;" ::"r"(d), "l"(gsrc),
                 "r"(srcsz));
}
__device__ __forceinline__ void cpa_commit() {
    asm volatile("cp.async.commit_group;");
}
__device__ __forceinline__ void cpa_wait1() {
    asm volatile("cp.async.wait_group 1;");
}

__device__ __forceinline__ uint32_t pack_h2(float a, float b) {
    __half2 h = __floats2half2_rn(a, b);
    return *(uint32_t*)&h;
}

// fp32 -> fp16, n multiple of 4
__global__ void f2h_kernel(const float* __restrict__ src, __half* __restrict__ dst,
                           int n) {
    int i = (blockIdx.x * blockDim.x + threadIdx.x) * 4;
    if (i < n) {
        float4 v = *(const float4*)(src + i);
        __half2 h0 = __floats2half2_rn(v.x, v.y);
        __half2 h1 = __floats2half2_rn(v.z, v.w);
        *(__half2*)(dst + i) = h0;
        *(__half2*)(dst + i + 2) = h1;
    }
}

// pack B[k][n] fp32 (row stride N) -> BP[k/2][n] u32 (row stride NP)
__global__ void packb_kernel(const float* __restrict__ B, uint32_t* __restrict__ BP,
                             int N, int NP) {
    int n = blockIdx.x * blockDim.x + threadIdx.x;
    int k2 = blockIdx.y;
    if (n < NP) {
        uint32_t out = 0;
        if (n < N)
            out = pack_h2(B[(size_t)(2 * k2) * N + n], B[(size_t)(2 * k2 + 1) * N + n]);
        BP[(size_t)k2 * NP + n] = out;
    }
}

// =====================================================================
// tgemm64: tf32, 64x64 tile, 128 threads (4 warps of 32x32), K-tile 32,
// 3-stage cp.async pipeline. Dynamic smem.
// =====================================================================
#define SM64 ((3 * 64 * 36 + 3 * 32 * 72) * 4)

template <class P>
__launch_bounds__(128)
__global__ void tgemm64(P p) {
    extern __shared__ float dsm64[];
    float(*As)[64][36] = (float(*)[64][36])dsm64;
    float(*Bs)[32][72] = (float(*)[32][72])(dsm64 + 3 * 64 * 36);

    const int tid = threadIdx.x;
    const int lane = tid & 31, wid = tid >> 5;
    const int wm = wid >> 1, wn = wid & 1;
    const int q = lane >> 2, t = lane & 3;
    const int m0 = blockIdx.y * 64;
    const int n0 = blockIdx.x * 64;

    float acc[2][4][4];
#pragma unroll
    for (int i = 0; i < 2; i++)
#pragma unroll
        for (int j = 0; j < 4; j++)
#pragma unroll
            for (int r = 0; r < 4; r++) acc[i][j][r] = 0.0f;

    auto fill = [&](int st, int k0) {
#pragma unroll
        for (int i = 0; i < 4; i++) {
            int c = tid + i * 128;
            int row = c >> 3, kp = (c & 7) << 2;
            cpa16(&As[st][row][kp], p.aChunk(m0 + row, k0 + kp));
        }
        p.copyB(&Bs[st][0][0], n0, k0, tid);
    };

    const int KT = p.K >> 5;
    fill(0, 0);
    cpa_commit();
    fill(1, 32);
    cpa_commit();

    for (int kt = 0; kt < KT; kt++) {
        cpa_wait1();
        __syncthreads();
        if (kt + 2 < KT) fill((kt + 2) % 3, (kt + 2) * 32);
        cpa_commit();
        const int st = kt % 3;

#pragma unroll
        for (int k8 = 0; k8 < 32; k8 += 8) {
            uint32_t af[2][4], bf[4][2];
#pragma unroll
            for (int ni = 0; ni < 4; ni++) {
                int nc = wn * 32 + ni * 8 + q;
                bf[ni][0] = __float_as_uint(Bs[st][k8 + t][nc]);
                bf[ni][1] = __float_as_uint(Bs[st][k8 + t + 4][nc]);
            }
#pragma unroll
            for (int mi = 0; mi < 2; mi++) {
                int mr = wm * 32 + mi * 16 + q;
                af[mi][0] = __float_as_uint(As[st][mr][k8 + t]);
                af[mi][1] = __float_as_uint(As[st][mr + 8][k8 + t]);
                af[mi][2] = __float_as_uint(As[st][mr][k8 + t + 4]);
                af[mi][3] = __float_as_uint(As[st][mr + 8][k8 + t + 4]);
            }
#pragma unroll
            for (int mi = 0; mi < 2; mi++)
#pragma unroll
                for (int ni = 0; ni < 4; ni++) mma8(acc[mi][ni], af[mi], bf[ni]);
        }
    }
    __syncthreads();
    p.store(acc, m0, n0, tid);
}

__device__ __forceinline__ void copyB64_dense(float* bs, const float* B, int ldb,
                                              int n0, int k0, int tid) {
#pragma unroll
    for (int i = 0; i < 4; i++) {
        int c = tid + i * 128;
        int k = c >> 4, np = (c & 15) << 2;
        cpa16(bs + k * 72 + np, B + (size_t)(k0 + k) * ldb + n0 + np);
    }
}

// ---------------- tgemm64 functors ----------------
struct Plain64 {
    const float* A;
    const float* B;
    const float* bias;
    float* C;
    int K;
    int N;
    int act;  // 0=none, 1=relu
    __device__ __forceinline__ const float* aChunk(int r, int k) const {
        return A + (size_t)r * K + k;
    }
    __device__ __forceinline__ void copyB(float* bs, int n0, int k0, int tid) const {
        copyB64_dense(bs, B, N, n0, k0, tid);
    }
    __device__ __forceinline__ void store(const float (&acc)[2][4][4], int m0, int n0,
                                          int tid) const {
        const int lane = tid & 31, wid = tid >> 5, wm = wid >> 1, wn = wid & 1;
#pragma unroll
        for (int mi = 0; mi < 2; mi++) {
            int r = m0 + wm * 32 + mi * 16 + (lane >> 2);
#pragma unroll
            for (int ni = 0; ni < 4; ni++) {
                int c = n0 + wn * 32 + ni * 8 + (lane & 3) * 2;
                float bx = bias[c], by = bias[c + 1];
                float2 lo = make_float2(acc[mi][ni][0] + bx, acc[mi][ni][1] + by);
                float2 hi = make_float2(acc[mi][ni][2] + bx, acc[mi][ni][3] + by);
                if (act == 1) {
                    lo.x = fmaxf(lo.x, 0.f);
                    lo.y = fmaxf(lo.y, 0.f);
                    hi.x = fmaxf(hi.x, 0.f);
                    hi.y = fmaxf(hi.y, 0.f);
                }
                *(float2*)(C + (size_t)r * N + c) = lo;
                *(float2*)(C + (size_t)(r + 8) * N + c) = hi;
            }
        }
    }
};

// relu + fp16 output (o1 -> o1h directly)
struct Plain64H {
    const float* A;
    const float* B;
    const float* bias;
    __half* C;
    int K;
    int N;
    __device__ __forceinline__ const float* aChunk(int r, int k) const {
        return A + (size_t)r * K + k;
    }
    __device__ __forceinline__ void copyB(float* bs, int n0, int k0, int tid) const {
        copyB64_dense(bs, B, N, n0, k0, tid);
    }
    __device__ __forceinline__ void store(const float (&acc)[2][4][4], int m0, int n0,
                                          int tid) const {
        const int lane = tid & 31, wid = tid >> 5, wm = wid >> 1, wn = wid & 1;
#pragma unroll
        for (int mi = 0; mi < 2; mi++) {
            int r = m0 + wm * 32 + mi * 16 + (lane >> 2);
#pragma unroll
            for (int ni = 0; ni < 4; ni++) {
                int c = n0 + wn * 32 + ni * 8 + (lane & 3) * 2;
                float bx = bias[c], by = bias[c + 1];
                __half2 lo = __floats2half2_rn(fmaxf(acc[mi][ni][0] + bx, 0.f),
                                               fmaxf(acc[mi][ni][1] + by, 0.f));
                __half2 hi = __floats2half2_rn(fmaxf(acc[mi][ni][2] + bx, 0.f),
                                               fmaxf(acc[mi][ni][3] + by, 0.f));
                *(__half2*)(C + (size_t)r * N + c) = lo;
                *(__half2*)(C + (size_t)(r + 8) * N + c) = hi;
            }
        }
    }
};

struct Comb64 {
    const float* emb;
    const int* ids;
    const float* ctx;
    const float* B;
    const float* bias;
    float* C;
    int K;
    __device__ __forceinline__ const float* aChunk(int r, int k) const {
        if (k < EDIM) return emb + (size_t)__ldg(&ids[r]) * EDIM + k;
        return ctx + (size_t)r * HDIM + (k - EDIM);
    }
    __device__ __forceinline__ void copyB(float* bs, int n0, int k0, int tid) const {
        copyB64_dense(bs, B, EDIM, n0, k0, tid);
    }
    __device__ __forceinline__ void store(const float (&acc)[2][4][4], int m0, int n0,
                                          int tid) const {
        const int lane = tid & 31, wid = tid >> 5, wm = wid >> 1, wn = wid & 1;
        const int N = EDIM;
#pragma unroll
        for (int mi = 0; mi < 2; mi++) {
            int r = m0 + wm * 32 + mi * 16 + (lane >> 2);
#pragma unroll
            for (int ni = 0; ni < 4; ni++) {
                int c = n0 + wn * 32 + ni * 8 + (lane & 3) * 2;
                float bx = bias[c], by = bias[c + 1];
                float2 lo = make_float2(fmaxf(acc[mi][ni][0] + bx, 0.f),
                                        fmaxf(acc[mi][ni][1] + by, 0.f));
                float2 hi = make_float2(fmaxf(acc[mi][ni][2] + bx, 0.f),
                                        fmaxf(acc[mi][ni][3] + by, 0.f));
                *(float2*)(C + (size_t)r * N + c) = lo;
                *(float2*)(C + (size_t)(r + 8) * N + c) = hi;
            }
        }
    }
};

struct Fused3_64 {
    const float* g;
    const float* hid;
    const float* ihw;
    const float* hhw;
    const float* candw;
    const float* hhcw;
    const float* ihb;
    const float* hhb;
    const float* candb;
    const float* hhcb;
    float* Cg;
    float* Ct1;
    float* Ct2;
    int K;
    __device__ __forceinline__ const float* aChunk(int r, int k) const {
        if (k < EDIM) return g + (size_t)r * EDIM + k;
        return hid + (size_t)r * HDIM + (k - EDIM);
    }
    __device__ __forceinline__ void copyB(float* bs, int n0, int k0, int tid) const {
#pragma unroll
        for (int i = 0; i < 4; i++) {
            int c = tid + i * 128;
            int k = c >> 4, np = (c & 15) << 2;
            int gk = k0 + k, gc = n0 + np;
            const float* src = ihw;
            int sz = 16;
            if (gc < 2048) {
                src = (gk < EDIM) ? ihw + (size_t)gk * 2048 + gc
                                  : hhw + (size_t)(gk - EDIM) * 2048 + gc;
            } else if (gc < 3072) {
                if (gk < EDIM) src = candw + (size_t)gk * HDIM + (gc - 2048);
                else sz = 0;
            } else {
                if (gk >= EDIM) src = hhcw + (size_t)(gk - EDIM) * HDIM + (gc - 3072);
                else sz = 0;
            }
            cpa16z(bs + k * 72 + np, src, sz);
        }
    }
    __device__ __forceinline__ void store(const float (&acc)[2][4][4], int m0, int n0,
                                          int tid) const {
        const int lane = tid & 31, wid = tid >> 5, wm = wid >> 1, wn = wid & 1;
        float* C;
        const float* b0p;
        const float* b1p;
        int N, cbase, sig;
        if (n0 < 2048) {
            C = Cg; N = 2048; cbase = n0; b0p = ihb; b1p = hhb; sig = 1;
        } else if (n0 < 3072) {
            C = Ct1; N = HDIM; cbase = n0 - 2048; b0p = candb; b1p = nullptr; sig = 0;
        } else {
            C = Ct2; N = HDIM; cbase = n0 - 3072; b0p = hhcb; b1p = nullptr; sig = 0;
        }
#pragma unroll
        for (int mi = 0; mi < 2; mi++) {
            int r = m0 + wm * 32 + mi * 16 + (lane >> 2);
#pragma unroll
            for (int ni = 0; ni < 4; ni++) {
                int c = cbase + wn * 32 + ni * 8 + (lane & 3) * 2;
                float bx = b0p[c], by = b0p[c + 1];
                if (b1p) { bx += b1p[c]; by += b1p[c + 1]; }
                float2 lo = make_float2(acc[mi][ni][0] + bx, acc[mi][ni][1] + by);
                float2 hi = make_float2(acc[mi][ni][2] + bx, acc[mi][ni][3] + by);
                if (sig) {
                    lo.x = 1.f / (1.f + expf(-lo.x));
                    lo.y = 1.f / (1.f + expf(-lo.y));
                    hi.x = 1.f / (1.f + expf(-hi.x));
                    hi.y = 1.f / (1.f + expf(-hi.y));
                }
                *(float2*)(C + (size_t)r * N + c) = lo;
                *(float2*)(C + (size_t)(r + 8) * N + c) = hi;
            }
        }
    }
};

// =====================================================================
// tgemm256h: fp16, 128x256 tile, 8 warps (64x64), K-tile 32, packed-u32 B
// via cp.async, double-buffered. Used by score only (round-8 proven).
// =====================================================================
#define AH_ST (128 * 20)
#define BH_ST (16 * 264)
#define SMEMH ((2 * AH_ST + 2 * BH_ST) * 4)

template <class P>
__launch_bounds__(256)
__global__ void tgemm256h(P p) {
    extern __shared__ uint32_t dsm[];
    uint32_t* Asm = dsm;
    uint32_t* Bsm = dsm + 2 * AH_ST;

    const int tid = threadIdx.x;
    const int lane = tid & 31, wid = tid >> 5;
    const int wm = wid >> 2, wn = wid & 3;
    const int q = lane >> 2, t = lane & 3;
    const int m0 = blockIdx.y * 128;
    const int n0 = blockIdx.x * 256;

    float acc[4][8][4];
#pragma unroll
    for (int i = 0; i < 4; i++)
#pragma unroll
        for (int j = 0; j < 8; j++)
#pragma unroll
            for (int r = 0; r < 4; r++) acc[i][j][r] = 0.0f;

    auto copyA = [&](int st, int k0) {
        uint32_t* ab = Asm + st * AH_ST;
#pragma unroll
        for (int i = 0; i < 2; i++) {
            int idx = tid + i * 256;
            int row = idx >> 2, c8 = (idx & 3);
            cpa16(ab + row * 20 + c8 * 4, p.aChunkH(m0 + row, k0 + c8 * 8));
        }
    };

    const int KT = p.K >> 5;
    copyA(0, 0);
    p.copyBP(Bsm, n0, 0, tid);
    cpa_commit();
    copyA(1, 32);
    p.copyBP(Bsm + BH_ST, n0, 32, tid);
    cpa_commit();

    for (int kt = 0; kt < KT; kt++) {
        cpa_wait1();
        __syncthreads();
        const int st = kt & 1;
        const uint32_t* ab = Asm + st * AH_ST;
        const uint32_t* bb = Bsm + st * BH_ST;

#pragma unroll
        for (int g = 0; g < 2; g++) {
            const int o = g * 8;
            uint32_t af[4][4], bf[8][2];
#pragma unroll
            for (int ni = 0; ni < 8; ni++) {
                int nc = wn * 64 + ni * 8 + q;
                bf[ni][0] = bb[(o + t) * 264 + nc];
                bf[ni][1] = bb[(o + t + 4) * 264 + nc];
            }
#pragma unroll
            for (int mi = 0; mi < 4; mi++) {
                int mr = wm * 64 + mi * 16 + q;
                af[mi][0] = ab[mr * 20 + o + t];
                af[mi][1] = ab[(mr + 8) * 20 + o + t];
                af[mi][2] = ab[mr * 20 + o + t + 4];
                af[mi][3] = ab[(mr + 8) * 20 + o + t + 4];
            }
#pragma unroll
            for (int mi = 0; mi < 4; mi++)
#pragma unroll
                for (int ni = 0; ni < 8; ni++) mma16(acc[mi][ni], af[mi], bf[ni]);
        }
        __syncthreads();
        if (kt + 2 < KT) {
            copyA(st, (kt + 2) * 32);
            p.copyBP(Bsm + st * BH_ST, n0, (kt + 2) * 32, tid);
        }
        cpa_commit();
    }
    p.store(acc, m0, n0, tid, (float*)dsm);
}

// score partial: part[nb][m] = sum_{c in 256-block nb} tanh(...) * vw[c]
struct ScoreH {
    const __half* encH;
    const uint32_t* UwP;
    const float* Wh;
    const float* Ub;
    const float* vw;
    float* part;  // [4][NSCORE]
    int K;
    __device__ __forceinline__ const __half* aChunkH(int r, int k) const {
        return encH + (size_t)r * HDIM + k;
    }
    __device__ __forceinline__ void copyBP(uint32_t* bs, int n0, int k0,
                                           int tid) const {
        const int k20 = k0 >> 1;
#pragma unroll
        for (int i = 0; i < 4; i++) {
            int idx = tid + i * 256;
            int k2 = idx >> 6, np = (idx & 63) << 2;
            cpa16(bs + k2 * 264 + np, UwP + (size_t)(k20 + k2) * HDIM + n0 + np);
        }
    }
    __device__ __forceinline__ void store(const float (&acc)[4][8][4], int m0, int n0,
                                          int tid, float* smem) const {
        float* red = smem;
        const int lane = tid & 31, wid = tid >> 5, wm = wid >> 2, wn = wid & 3;
        const int q = lane >> 2, t = lane & 3;
        __syncthreads();
#pragma unroll
        for (int mi = 0; mi < 4; mi++) {
            int r0 = m0 + wm * 64 + mi * 16 + q;
            const float* wh0 = Wh + (size_t)(r0 & (BATCH - 1)) * HDIM;
            const float* wh1 = Wh + (size_t)((r0 + 8) & (BATCH - 1)) * HDIM;
            float s0 = 0.f, s1 = 0.f;
#pragma unroll
            for (int ni = 0; ni < 8; ni++) {
                int c = n0 + wn * 64 + ni * 8 + t * 2;
                float u0 = Ub[c], u1 = Ub[c + 1];
                float w0 = vw[c], w1 = vw[c + 1];
                s0 += tanhf(acc[mi][ni][0] + wh0[c] + u0) * w0;
                s0 += tanhf(acc[mi][ni][1] + wh0[c + 1] + u1) * w1;
                s1 += tanhf(acc[mi][ni][2] + wh1[c] + u0) * w0;
                s1 += tanhf(acc[mi][ni][3] + wh1[c + 1] + u1) * w1;
            }
            s0 += __shfl_xor_sync(0xffffffffu, s0, 1);
            s0 += __shfl_xor_sync(0xffffffffu, s0, 2);
            s1 += __shfl_xor_sync(0xffffffffu, s1, 1);
            s1 += __shfl_xor_sync(0xffffffffu, s1, 2);
            if (t == 0) {
                red[wn * 128 + wm * 64 + mi * 16 + q] = s0;
                red[wn * 128 + wm * 64 + mi * 16 + q + 8] = s1;
            }
        }
        __syncthreads();
        if (tid < 128)
            part[(size_t)(n0 >> 8) * NSCORE + m0 + tid] =
                red[tid] + red[128 + tid] + red[256 + tid] + red[384 + tid];
    }
};

// =====================================================================
// out2 GEMM: fp16 mma, B staged as RAW fp32 via 4-BYTE cp.async.
// Epilogue: stores logits AND per-block row max / sumexp partials.
// =====================================================================
#define BO_ST (32 * 260)
#define SMEMO ((2 * AH_ST + 2 * BO_ST) * 4)

__launch_bounds__(256)
__global__ void out2_gemm(const __half* __restrict__ AH,
                          const float* __restrict__ B,
                          const float* __restrict__ bias,
                          float* __restrict__ C,
                          float* __restrict__ lmax,
                          float* __restrict__ lsum) {
    extern __shared__ uint32_t dsm[];
    uint32_t* Asm = dsm;                    // [2][AH_ST]
    float* Bf = (float*)(dsm + 2 * AH_ST);  // [2][BO_ST]

    const int tid = threadIdx.x;
    const int lane = tid & 31, wid = tid >> 5;
    const int wm = wid >> 2, wn = wid & 3;
    const int q = lane >> 2, t = lane & 3;
    const int m0 = blockIdx.x * 128;  // m fastest
    const int n0 = blockIdx.y * 256;
    const int nb = blockIdx.y;

    float acc[4][8][4];
#pragma unroll
    for (int i = 0; i < 4; i++)
#pragma unroll
        for (int j = 0; j < 8; j++)
#pragma unroll
            for (int r = 0; r < 4; r++) acc[i][j][r] = 0.0f;

    auto copyA = [&](int st, int k0) {
        uint32_t* ab = Asm + st * AH_ST;
#pragma unroll
        for (int i = 0; i < 2; i++) {
            int idx = tid + i * 256;
            int row = idx >> 2, c8 = (idx & 3);
            cpa16(ab + row * 20 + c8 * 4, AH + (size_t)(m0 + row) * HDIM + k0 + c8 * 8);
        }
    };
    auto copyB = [&](int st, int k0) {
        float* bb = Bf + st * BO_ST;
#pragma unroll
        for (int i = 0; i < 32; i++) {
            int idx = tid + i * 256;  // 8192 words: 32 k-rows x 256
            int k = idx >> 8, n = idx & 255;
            int gn = n0 + n;
            int ok = gn < VDIM;
            const float* src = B + (size_t)(k0 + k) * VDIM + (ok ? gn : 0);
            cpa4z(bb + k * 260 + n, src, ok ? 4 : 0);
        }
    };

    const int KT = HDIM >> 5;
    copyA(0, 0);
    copyB(0, 0);
    cpa_commit();
    copyA(1, 32);
    copyB(1, 32);
    cpa_commit();

    for (int kt = 0; kt < KT; kt++) {
        cpa_wait1();
        __syncthreads();
        const int st = kt & 1;
        const uint32_t* ab = Asm + st * AH_ST;
        const float* bb = Bf + st * BO_ST;

#pragma unroll
        for (int g = 0; g < 2; g++) {  // two k16 groups
            const int o = g * 16;      // fp32 row base
            uint32_t af[4][4], bf[8][2];
#pragma unroll
            for (int ni = 0; ni < 8; ni++) {
                int nc = wn * 64 + ni * 8 + q;
                bf[ni][0] = pack_h2(bb[(o + 2 * t) * 260 + nc],
                                    bb[(o + 2 * t + 1) * 260 + nc]);
                bf[ni][1] = pack_h2(bb[(o + 2 * t + 8) * 260 + nc],
                                    bb[(o + 2 * t + 9) * 260 + nc]);
            }
#pragma unroll
            for (int mi = 0; mi < 4; mi++) {
                int mr = wm * 64 + mi * 16 + q;
                af[mi][0] = ab[mr * 20 + g * 8 + t];
                af[mi][1] = ab[(mr + 8) * 20 + g * 8 + t];
                af[mi][2] = ab[mr * 20 + g * 8 + t + 4];
                af[mi][3] = ab[(mr + 8) * 20 + g * 8 + t + 4];
            }
#pragma unroll
            for (int mi = 0; mi < 4; mi++)
#pragma unroll
                for (int ni = 0; ni < 8; ni++) mma16(acc[mi][ni], af[mi], bf[ni]);
        }
        __syncthreads();
        if (kt + 2 < KT) {
            copyA(st, (kt + 2) * 32);
            copyB(st, (kt + 2) * 32);
        }
        cpa_commit();
    }

    // ---- epilogue: store logits + block-row max / sumexp ----
    __syncthreads();
    float* redm = (float*)dsm;  // [4][128]
    float* bmax = redm + 512;   // [128]

#pragma unroll
    for (int mi = 0; mi < 4; mi++) {
#pragma unroll
        for (int half = 0; half < 2; half++) {
            int rl = wm * 64 + mi * 16 + q + half * 8;
            int r = m0 + rl;
            float mx = -3.4e38f;
#pragma unroll
            for (int ni = 0; ni < 8; ni++) {
                int c0 = n0 + wn * 64 + ni * 8 + t * 2;
                if (c0 < VDIM) {
                    float v0 = acc[mi][ni][half * 2 + 0] + bias[c0];
                    C[(size_t)r * VDIM + c0] = v0;
                    mx = fmaxf(mx, v0);
                }
                if (c0 + 1 < VDIM) {
                    float v1 = acc[mi][ni][half * 2 + 1] + bias[c0 + 1];
                    C[(size_t)r * VDIM + c0 + 1] = v1;
                    mx = fmaxf(mx, v1);
                }
            }
            mx = fmaxf(mx, __shfl_xor_sync(0xffffffffu, mx, 1));
            mx = fmaxf(mx, __shfl_xor_sync(0xffffffffu, mx, 2));
            if (t == 0) redm[wn * 128 + rl] = mx;
        }
    }
    __syncthreads();
    if (tid < 128)
        bmax[tid] = fmaxf(fmaxf(redm[tid], redm[128 + tid]),
                          fmaxf(redm[256 + tid], redm[384 + tid]));
    __syncthreads();

#pragma unroll
    for (int mi = 0; mi < 4; mi++) {
#pragma unroll
        for (int half = 0; half < 2; half++) {
            int rl = wm * 64 + mi * 16 + q + half * 8;
            float bm = bmax[rl];
            float s = 0.f;
#pragma unroll
            for (int ni = 0; ni < 8; ni++) {
                int c0 = n0 + wn * 64 + ni * 8 + t * 2;
                if (c0 < VDIM) s += expf(acc[mi][ni][half * 2 + 0] + bias[c0] - bm);
                if (c0 + 1 < VDIM)
                    s += expf(acc[mi][ni][half * 2 + 1] + bias[c0 + 1] - bm);
            }
            s += __shfl_xor_sync(0xffffffffu, s, 1);
            s += __shfl_xor_sync(0xffffffffu, s, 2);
            if (t == 0) redm[wn * 128 + rl] = s;
        }
    }
    __syncthreads();
    if (tid < 128) {
        lmax[(size_t)nb * BATCH + m0 + tid] = bmax[tid];
        lsum[(size_t)nb * BATCH + m0 + tid] =
            redm[tid] + redm[128 + tid] + redm[256 + tid] + redm[384 + tid];
    }
}

// ---------------- fused softmax(S) + context (reads fp16 enc) ----------------
__global__ void softmax_ctx_kernel(const float* __restrict__ part,
                                   const __half* __restrict__ encH,
                                   float* __restrict__ attn_out,
                                   float* __restrict__ ctx) {
    const int n = blockIdx.x;
    const int tid = threadIdx.x;  // 256
    __shared__ float a[SDIM];
    __shared__ float rmax[4], rsum[4];

    float v = 0.f, e = 0.f;
    if (tid < SDIM) {
        const int idx = tid * BATCH + n;
        v = part[idx] + part[NSCORE + idx] + part[2 * NSCORE + idx] +
            part[3 * NSCORE + idx];
        float m = warp_max(v);
        if ((tid & 31) == 0) rmax[tid >> 5] = m;
    }
    __syncthreads();
    if (tid < SDIM) {
        float m = fmaxf(fmaxf(rmax[0], rmax[1]), fmaxf(rmax[2], rmax[3]));
        e = expf(v - m);
        float s = warp_sum(e);
        if ((tid & 31) == 0) rsum[tid >> 5] = s;
    }
    __syncthreads();
    if (tid < SDIM) {
        float sum = rsum[0] + rsum[1] + rsum[2] + rsum[3];
        float av = e / sum;
        attn_out[tid * BATCH + n] = av;
        a[tid] = av;
    }
    __syncthreads();

    float4 acc = make_float4(0.f, 0.f, 0.f, 0.f);
    for (int s = 0; s < SDIM; s++) {
        const __half2* ep =
            (const __half2*)(encH + ((size_t)s * BATCH + n) * HDIM) + tid * 2;
        float2 f0 = __half22float2(ep[0]);
        float2 f1 = __half22float2(ep[1]);
        float w = a[s];
        acc.x = fmaf(w, f0.x, acc.x);
        acc.y = fmaf(w, f0.y, acc.y);
        acc.z = fmaf(w, f1.x, acc.z);
        acc.w = fmaf(w, f1.y, acc.w);
    }
    ((float4*)(ctx + (size_t)n * HDIM))[tid] = acc;
}

// ---------------- GRU combine + LayerNorm ----------------
__global__ void fuse_hln_kernel(const float* __restrict__ gates,
                                const float* __restrict__ t1,
                                const float* __restrict__ t2,
                                const float* __restrict__ hid,
                                const float* __restrict__ lng,
                                const float* __restrict__ lnb,
                                float* __restrict__ hout) {
    const int n = blockIdx.x;
    const int tid = threadIdx.x;  // 256
    float4 z = ((const float4*)(gates + (size_t)n * 2 * HDIM))[tid];
    float4 r = ((const float4*)(gates + (size_t)n * 2 * HDIM + HDIM))[tid];
    float4 a = ((const float4*)(t1 + (size_t)n * HDIM))[tid];
    float4 b = ((const float4*)(t2 + (size_t)n * HDIM))[tid];
    float4 hv = ((const float4*)(hid + (size_t)n * HDIM))[tid];
    float4 hr;
    hr.x = (1.0f - z.x) * hv.x + z.x * tanhf(a.x + r.x * b.x);
    hr.y = (1.0f - z.y) * hv.y + z.y * tanhf(a.y + r.y * b.y);
    hr.z = (1.0f - z.z) * hv.z + z.z * tanhf(a.z + r.z * b.z);
    hr.w = (1.0f - z.w) * hv.w + z.w * tanhf(a.w + r.w * b.w);
    float s = hr.x + hr.y + hr.z + hr.w;
    float ss = hr.x * hr.x + hr.y * hr.y + hr.z * hr.z + hr.w * hr.w;
    __shared__ float sm1[8], sm2[8];
    float w1 = warp_sum(s), w2 = warp_sum(ss);
    if ((tid & 31) == 0) { sm1[tid >> 5] = w1; sm2[tid >> 5] = w2; }
    __syncthreads();
    float tot1 = 0.f, tot2 = 0.f;
#pragma unroll
    for (int qq = 0; qq < 8; qq++) { tot1 += sm1[qq]; tot2 += sm2[qq]; }
    float mu = tot1 * (1.0f / HDIM);
    float var = tot2 * (1.0f / HDIM) - mu * mu;
    float inv = rsqrtf(var + 1e-5f);
    float4 gg = ((const float4*)lng)[tid];
    float4 bb = ((const float4*)lnb)[tid];
    float4 o;
    o.x = (hr.x - mu) * inv * gg.x + bb.x;
    o.y = (hr.y - mu) * inv * gg.y + bb.y;
    o.z = (hr.z - mu) * inv * gg.z + bb.z;
    o.w = (hr.w - mu) * inv * gg.w + bb.w;
    ((float4*)(hout + (size_t)n * HDIM))[tid] = o;
}

// ---------------- final log_softmax: reduce partials + single RW pass ---------
__global__ void logsoftmax2_kernel(float* __restrict__ logits,
                                   const float* __restrict__ lmax,
                                   const float* __restrict__ lsum) {
    const int n = blockIdx.x;
    const int tid = threadIdx.x;  // 512
    __shared__ float sm[16];

    float m = -3.4e38f;
    for (int i = tid; i < NB2; i += 512) m = fmaxf(m, lmax[(size_t)i * BATCH + n]);
    m = warp_max(m);
    if ((tid & 31) == 0) sm[tid >> 5] = m;
    __syncthreads();
    float gmax = -3.4e38f;
#pragma unroll
    for (int qq = 0; qq < 16; qq++) gmax = fmaxf(gmax, sm[qq]);
    __syncthreads();

    float s = 0.f;
    for (int i = tid; i < NB2; i += 512)
        s += lsum[(size_t)i * BATCH + n] * expf(lmax[(size_t)i * BATCH + n] - gmax);
    s = warp_sum(s);
    if ((tid & 31) == 0) sm[tid >> 5] = s;
    __syncthreads();
    float tot = 0.f;
#pragma unroll
    for (int qq = 0; qq < 16; qq++) tot += sm[qq];
    float lse = gmax + logf(tot);

    float* row = logits + (size_t)n * VDIM;
    for (int i = tid; i < VDIM; i += 512) row[i] -= lse;
}

// ---------------- launch ----------------
extern "C" void kernel_launch(void* const* d_in, const int* in_sizes, int n_in,
                              void* d_out, int out_size) {
    const int* ids = (const int*)d_in[0];
    const float* hidden = (const float*)d_in[1];
    const float* enc = (const float*)d_in[2];
    const float* emb = (const float*)d_in[3];
    const float* W_w = (const float*)d_in[4];
    const float* W_b = (const float*)d_in[5];
    const float* U_w = (const float*)d_in[6];
    const float* U_b = (const float*)d_in[7];
    const float* v_w = (const float*)d_in[8];
    // d_in[9] = v_b : constant over S, cancels in softmax
    const float* ih_w = (const float*)d_in[10];
    const float* ih_b = (const float*)d_in[11];
    const float* hh_w = (const float*)d_in[12];
    const float* hh_b = (const float*)d_in[13];
    const float* cand_w = (const float*)d_in[14];
    const float* cand_b = (const float*)d_in[15];
    const float* hhc_w = (const float*)d_in[16];
    const float* hhc_b = (const float*)d_in[17];
    const float* comb_w = (const float*)d_in[18];
    const float* comb_b = (const float*)d_in[19];
    const float* ln_g = (const float*)d_in[20];
    const float* ln_b = (const float*)d_in[21];
    const float* out1_w = (const float*)d_in[22];
    const float* out1_b = (const float*)d_in[23];
    const float* out2_w = (const float*)d_in[24];
    const float* out2_b = (const float*)d_in[25];

    float* out_logits = (float*)d_out;
    float* out_h = out_logits + (size_t)BATCH * VDIM;
    float* out_attn = out_h + (size_t)BATCH * HDIM;

    float *Wh, *score4, *ctx, *gbuf, *gates, *t1, *t2, *lmax, *lsum;
    __half *encH, *o1h;
    uint32_t* UwP;
    cudaGetSymbolAddress((void**)&Wh, g_Wh);
    cudaGetSymbolAddress((void**)&score4, g_score4);
    cudaGetSymbolAddress((void**)&ctx, g_ctx);
    cudaGetSymbolAddress((void**)&gbuf, g_g);
    cudaGetSymbolAddress((void**)&gates, g_gates);
    cudaGetSymbolAddress((void**)&t1, g_t1);
    cudaGetSymbolAddress((void**)&t2, g_t2);
    cudaGetSymbolAddress((void**)&encH, g_encH);
    cudaGetSymbolAddress((void**)&o1h, g_o1h);
    cudaGetSymbolAddress((void**)&UwP, g_UwP);
    cudaGetSymbolAddress((void**)&lmax, g_lmax);
    cudaGetSymbolAddress((void**)&lsum, g_lsum);

    cudaFuncSetAttribute(tgemm256h<ScoreH>,
                         cudaFuncAttributeMaxDynamicSharedMemorySize, SMEMH);
    cudaFuncSetAttribute(out2_gemm, cudaFuncAttributeMaxDynamicSharedMemorySize,
                         SMEMO);
    cudaFuncSetAttribute(tgemm64<Plain64>,
                         cudaFuncAttributeMaxDynamicSharedMemorySize, SM64);
    cudaFuncSetAttribute(tgemm64<Plain64H>,
                         cudaFuncAttributeMaxDynamicSharedMemorySize, SM64);
    cudaFuncSetAttribute(tgemm64<Comb64>,
                         cudaFuncAttributeMaxDynamicSharedMemorySize, SM64);
    cudaFuncSetAttribute(tgemm64<Fused3_64>,
                         cudaFuncAttributeMaxDynamicSharedMemorySize, SM64);

    // ---- forked pre-score phase: f2h_enc on side stream, packb+Wh on main ----
    cudaStream_t side;
    cudaStreamCreateWithFlags(&side, cudaStreamNonBlocking);
    cudaEvent_t evFork, evJoin;
    cudaEventCreateWithFlags(&evFork, cudaEventDisableTiming);
    cudaEventCreateWithFlags(&evJoin, cudaEventDisableTiming);

    cudaEventRecord(evFork, 0);
    cudaStreamWaitEvent(side, evFork, 0);
    f2h_kernel<<<(SDIM * BATCH * HDIM) / 1024, 256, 0, side>>>(
        enc, encH, SDIM * BATCH * HDIM);
    cudaEventRecord(evJoin, side);

    packb_kernel<<<dim3(HDIM / 256, HDIM / 2), 256>>>(U_w, UwP, HDIM, HDIM);
    {
        Plain64 p{hidden, W_w, W_b, Wh, HDIM, HDIM, 0};
        tgemm64<Plain64><<<dim3(HDIM / 64, BATCH / 64), 128, SM64>>>(p);
    }
    cudaStreamWaitEvent(0, evJoin, 0);

    // 2. fused score GEMM -> 4 partial buffers
    {
        ScoreH p{encH, UwP, Wh, U_b, v_w, score4, HDIM};
        tgemm256h<ScoreH><<<dim3(HDIM / 256, (SDIM * BATCH) / 128), 256, SMEMH>>>(p);
    }
    // 3. fused softmax + context (fp16 enc)
    softmax_ctx_kernel<<<BATCH, 256>>>(score4, encH, out_attn, ctx);
    // 4. g = relu([emb[ids], ctx] @ comb_w + comb_b)
    {
        Comb64 p{emb, ids, ctx, comb_w, comb_b, gbuf, EDIM + HDIM};
        tgemm64<Comb64><<<dim3(EDIM / 64, BATCH / 64), 128, SM64>>>(p);
    }
    // 5. fused gates | t1 | t2
    {
        Fused3_64 p{gbuf, hidden, ih_w, hh_w, cand_w, hhc_w,
                    ih_b, hh_b, cand_b, hhc_b, gates, t1, t2, EDIM + HDIM};
        tgemm64<Fused3_64><<<dim3(4096 / 64, BATCH / 64), 128, SM64>>>(p);
    }
    // 6. GRU combine + LayerNorm
    fuse_hln_kernel<<<BATCH, 256>>>(gates, t1, t2, hidden, ln_g, ln_b, out_h);
    // 7. o1h = relu(h @ out1_w + out1_b) directly in fp16
    {
        Plain64H p{out_h, out1_w, out1_b, o1h, HDIM, HDIM};
        tgemm64<Plain64H><<<dim3(HDIM / 64, BATCH / 64), 128, SM64>>>(p);
    }
    // 8. logits + fused log-softmax partials
    out2_gemm<<<dim3(BATCH / 128, NB2), 256, SMEMO>>>(o1h, out2_w, out2_b, out_logits,
                                                      lmax, lsum);
    // 9. final log_softmax: reduce partials + single pass
    logsoftmax2_kernel<<<BATCH, 512>>>(out_logits, lmax, lsum);

    cudaStreamDestroy(side);
    cudaEventDestroy(evFork);
    cudaEventDestroy(evJoin);
}

// round 16
// speedup vs baseline: 1.1101x; 1.0200x over previous
#include <cuda_runtime.h>
#include <cuda_fp16.h>
#include <cstdint>

#define BATCH 256
#define HDIM  1024
#define EDIM  512
#define SDIM  128
#define VDIM  50257
#define NSCORE (SDIM * BATCH)
#define NB2 ((VDIM + 255) / 256)  // 197 out2 n-blocks

// ---------------- scratch (no allocations allowed) ----------------
__device__ float g_Wh[BATCH * HDIM];
__device__ float g_score4[4 * NSCORE];  // per-nblock score partials
__device__ float g_ctx[BATCH * HDIM];
__device__ float g_g[BATCH * EDIM];
__device__ float g_gates[BATCH * 2 * HDIM];
__device__ float g_t1[BATCH * HDIM];
__device__ float g_t2[BATCH * HDIM];
__device__ __half g_encH[SDIM * BATCH * HDIM];  // enc as fp16
__device__ __half g_o1h[BATCH * HDIM];          // o1 as fp16
__device__ uint32_t g_UwP[(HDIM / 2) * HDIM];   // U_w k-pair packed fp16
__device__ float g_lmax[NB2 * BATCH];           // out2 per-block row max
__device__ float g_lsum[NB2 * BATCH];           // out2 per-block row sumexp

// ---------------- helpers ----------------
__device__ __forceinline__ float warp_sum(float v) {
#pragma unroll
    for (int o = 16; o > 0; o >>= 1) v += __shfl_xor_sync(0xffffffffu, v, o);
    return v;
}
__device__ __forceinline__ float warp_max(float v) {
#pragma unroll
    for (int o = 16; o > 0; o >>= 1) v = fmaxf(v, __shfl_xor_sync(0xffffffffu, v, o));
    return v;
}

__device__ __forceinline__ void mma8(float* c, const uint32_t* a, const uint32_t* b) {
    asm volatile(
        "mma.sync.aligned.m16n8k8.row.col.f32.tf32.tf32.f32 "
        "{%0,%1,%2,%3}, {%4,%5,%6,%7}, {%8,%9}, {%0,%1,%2,%3};"
        : "+f"(c[0]), "+f"(c[1]), "+f"(c[2]), "+f"(c[3])
        : "r"(a[0]), "r"(a[1]), "r"(a[2]), "r"(a[3]), "r"(b[0]), "r"(b[1]));
}
__device__ __forceinline__ void mma16(float* c, const uint32_t* a, const uint32_t* b) {
    asm volatile(
        "mma.sync.aligned.m16n8k16.row.col.f32.f16.f16.f32 "
        "{%0,%1,%2,%3}, {%4,%5,%6,%7}, {%8,%9}, {%0,%1,%2,%3};"
        : "+f"(c[0]), "+f"(c[1]), "+f"(c[2]), "+f"(c[3])
        : "r"(a[0]), "r"(a[1]), "r"(a[2]), "r"(a[3]), "r"(b[0]), "r"(b[1]));
}

__device__ __forceinline__ void cpa16(void* smem_dst, const void* gsrc) {
    uint32_t d = (uint32_t)__cvta_generic_to_shared(smem_dst);
    asm volatile("cp.async.ca.shared.global [%0], [%1], 16;" ::"r"(d), "l"(gsrc));
}
__device__ __forceinline__ void cpa16z(void* smem_dst, const void* gsrc, int srcsz) {
    uint32_t d = (uint32_t)__cvta_generic_to_shared(smem_dst);
    asm volatile("cp.async.ca.shared.global [%0], [%1], 16, %2;" ::"r"(d), "l"(gsrc),
                 "r"(srcsz));
}
__device__ __forceinline__ void cpa4z(void* smem_dst, const void* gsrc, int srcsz) {
    uint32_t d = (uint32_t)__cvta_generic_to_shared(smem_dst);
    asm volatile("cp.async.ca.shared.global [%0], [%1], 4, %2;" ::"r"(d), "l"(gsrc),
                 "r"(srcsz));
}
__device__ __forceinline__ void cpa_commit() {
    asm volatile("cp.async.commit_group;");
}
__device__ __forceinline__ void cpa_wait1() {
    asm volatile("cp.async.wait_group 1;");
}

__device__ __forceinline__ uint32_t pack_h2(float a, float b) {
    __half2 h = __floats2half2_rn(a, b);
    return *(uint32_t*)&h;
}

// fp32 -> fp16, n multiple of 4
__global__ void f2h_kernel(const float* __restrict__ src, __half* __restrict__ dst,
                           int n) {
    int i = (blockIdx.x * blockDim.x + threadIdx.x) * 4;
    if (i < n) {
        float4 v = *(const float4*)(src + i);
        __half2 h0 = __floats2half2_rn(v.x, v.y);
        __half2 h1 = __floats2half2_rn(v.z, v.w);
        *(__half2*)(dst + i) = h0;
        *(__half2*)(dst + i + 2) = h1;
    }
}

// pack B[k][n] fp32 (row stride N) -> BP[k/2][n] u32 (row stride NP)
__global__ void packb_kernel(const float* __restrict__ B, uint32_t* __restrict__ BP,
                             int N, int NP) {
    int n = blockIdx.x * blockDim.x + threadIdx.x;
    int k2 = blockIdx.y;
    if (n < NP) {
        uint32_t out = 0;
        if (n < N)
            out = pack_h2(B[(size_t)(2 * k2) * N + n], B[(size_t)(2 * k2 + 1) * N + n]);
        BP[(size_t)k2 * NP + n] = out;
    }
}

// =====================================================================
// tgemm64: tf32, 64x64 tile, 128 threads (4 warps of 32x32), K-tile 32,
// 3-stage cp.async pipeline. Dynamic smem.
// =====================================================================
#define SM64 ((3 * 64 * 36 + 3 * 32 * 72) * 4)

template <class P>
__launch_bounds__(128)
__global__ void tgemm64(P p) {
    extern __shared__ float dsm64[];
    float(*As)[64][36] = (float(*)[64][36])dsm64;
    float(*Bs)[32][72] = (float(*)[32][72])(dsm64 + 3 * 64 * 36);

    const int tid = threadIdx.x;
    const int lane = tid & 31, wid = tid >> 5;
    const int wm = wid >> 1, wn = wid & 1;
    const int q = lane >> 2, t = lane & 3;
    const int m0 = blockIdx.y * 64;
    const int n0 = blockIdx.x * 64;

    float acc[2][4][4];
#pragma unroll
    for (int i = 0; i < 2; i++)
#pragma unroll
        for (int j = 0; j < 4; j++)
#pragma unroll
            for (int r = 0; r < 4; r++) acc[i][j][r] = 0.0f;

    auto fill = [&](int st, int k0) {
#pragma unroll
        for (int i = 0; i < 4; i++) {
            int c = tid + i * 128;
            int row = c >> 3, kp = (c & 7) << 2;
            cpa16(&As[st][row][kp], p.aChunk(m0 + row, k0 + kp));
        }
        p.copyB(&Bs[st][0][0], n0, k0, tid);
    };

    const int KT = p.K >> 5;
    fill(0, 0);
    cpa_commit();
    fill(1, 32);
    cpa_commit();

    for (int kt = 0; kt < KT; kt++) {
        cpa_wait1();
        __syncthreads();
        if (kt + 2 < KT) fill((kt + 2) % 3, (kt + 2) * 32);
        cpa_commit();
        const int st = kt % 3;

#pragma unroll
        for (int k8 = 0; k8 < 32; k8 += 8) {
            uint32_t af[2][4], bf[4][2];
#pragma unroll
            for (int ni = 0; ni < 4; ni++) {
                int nc = wn * 32 + ni * 8 + q;
                bf[ni][0] = __float_as_uint(Bs[st][k8 + t][nc]);
                bf[ni][1] = __float_as_uint(Bs[st][k8 + t + 4][nc]);
            }
#pragma unroll
            for (int mi = 0; mi < 2; mi++) {
                int mr = wm * 32 + mi * 16 + q;
                af[mi][0] = __float_as_uint(As[st][mr][k8 + t]);
                af[mi][1] = __float_as_uint(As[st][mr + 8][k8 + t]);
                af[mi][2] = __float_as_uint(As[st][mr][k8 + t + 4]);
                af[mi][3] = __float_as_uint(As[st][mr + 8][k8 + t + 4]);
            }
#pragma unroll
            for (int mi = 0; mi < 2; mi++)
#pragma unroll
                for (int ni = 0; ni < 4; ni++) mma8(acc[mi][ni], af[mi], bf[ni]);
        }
    }
    __syncthreads();
    p.store(acc, m0, n0, tid);
}

__device__ __forceinline__ void copyB64_dense(float* bs, const float* B, int ldb,
                                              int n0, int k0, int tid) {
#pragma unroll
    for (int i = 0; i < 4; i++) {
        int c = tid + i * 128;
        int k = c >> 4, np = (c & 15) << 2;
        cpa16(bs + k * 72 + np, B + (size_t)(k0 + k) * ldb + n0 + np);
    }
}

// ---------------- tgemm64 functors ----------------
struct Plain64 {
    const float* A;
    const float* B;
    const float* bias;
    float* C;
    int K;
    int N;
    int act;  // 0=none, 1=relu
    __device__ __forceinline__ const float* aChunk(int r, int k) const {
        return A + (size_t)r * K + k;
    }
    __device__ __forceinline__ void copyB(float* bs, int n0, int k0, int tid) const {
        copyB64_dense(bs, B, N, n0, k0, tid);
    }
    __device__ __forceinline__ void store(const float (&acc)[2][4][4], int m0, int n0,
                                          int tid) const {
        const int lane = tid & 31, wid = tid >> 5, wm = wid >> 1, wn = wid & 1;
#pragma unroll
        for (int mi = 0; mi < 2; mi++) {
            int r = m0 + wm * 32 + mi * 16 + (lane >> 2);
#pragma unroll
            for (int ni = 0; ni < 4; ni++) {
                int c = n0 + wn * 32 + ni * 8 + (lane & 3) * 2;
                float bx = bias[c], by = bias[c + 1];
                float2 lo = make_float2(acc[mi][ni][0] + bx, acc[mi][ni][1] + by);
                float2 hi = make_float2(acc[mi][ni][2] + bx, acc[mi][ni][3] + by);
                if (act == 1) {
                    lo.x = fmaxf(lo.x, 0.f);
                    lo.y = fmaxf(lo.y, 0.f);
                    hi.x = fmaxf(hi.x, 0.f);
                    hi.y = fmaxf(hi.y, 0.f);
                }
                *(float2*)(C + (size_t)r * N + c) = lo;
                *(float2*)(C + (size_t)(r + 8) * N + c) = hi;
            }
        }
    }
};

// relu + fp16 output (o1 -> o1h directly)
struct Plain64H {
    const float* A;
    const float* B;
    const float* bias;
    __half* C;
    int K;
    int N;
    __device__ __forceinline__ const float* aChunk(int r, int k) const {
        return A + (size_t)r * K + k;
    }
    __device__ __forceinline__ void copyB(float* bs, int n0, int k0, int tid) const {
        copyB64_dense(bs, B, N, n0, k0, tid);
    }
    __device__ __forceinline__ void store(const float (&acc)[2][4][4], int m0, int n0,
                                          int tid) const {
        const int lane = tid & 31, wid = tid >> 5, wm = wid >> 1, wn = wid & 1;
#pragma unroll
        for (int mi = 0; mi < 2; mi++) {
            int r = m0 + wm * 32 + mi * 16 + (lane >> 2);
#pragma unroll
            for (int ni = 0; ni < 4; ni++) {
                int c = n0 + wn * 32 + ni * 8 + (lane & 3) * 2;
                float bx = bias[c], by = bias[c + 1];
                __half2 lo = __floats2half2_rn(fmaxf(acc[mi][ni][0] + bx, 0.f),
                                               fmaxf(acc[mi][ni][1] + by, 0.f));
                __half2 hi = __floats2half2_rn(fmaxf(acc[mi][ni][2] + bx, 0.f),
                                               fmaxf(acc[mi][ni][3] + by, 0.f));
                *(__half2*)(C + (size_t)r * N + c) = lo;
                *(__half2*)(C + (size_t)(r + 8) * N + c) = hi;
            }
        }
    }
};

struct Comb64 {
    const float* emb;
    const int* ids;
    const float* ctx;
    const float* B;
    const float* bias;
    float* C;
    int K;
    __device__ __forceinline__ const float* aChunk(int r, int k) const {
        if (k < EDIM) return emb + (size_t)__ldg(&ids[r]) * EDIM + k;
        return ctx + (size_t)r * HDIM + (k - EDIM);
    }
    __device__ __forceinline__ void copyB(float* bs, int n0, int k0, int tid) const {
        copyB64_dense(bs, B, EDIM, n0, k0, tid);
    }
    __device__ __forceinline__ void store(const float (&acc)[2][4][4], int m0, int n0,
                                          int tid) const {
        const int lane = tid & 31, wid = tid >> 5, wm = wid >> 1, wn = wid & 1;
        const int N = EDIM;
#pragma unroll
        for (int mi = 0; mi < 2; mi++) {
            int r = m0 + wm * 32 + mi * 16 + (lane >> 2);
#pragma unroll
            for (int ni = 0; ni < 4; ni++) {
                int c = n0 + wn * 32 + ni * 8 + (lane & 3) * 2;
                float bx = bias[c], by = bias[c + 1];
                float2 lo = make_float2(fmaxf(acc[mi][ni][0] + bx, 0.f),
                                        fmaxf(acc[mi][ni][1] + by, 0.f));
                float2 hi = make_float2(fmaxf(acc[mi][ni][2] + bx, 0.f),
                                        fmaxf(acc[mi][ni][3] + by, 0.f));
                *(float2*)(C + (size_t)r * N + c) = lo;
                *(float2*)(C + (size_t)(r + 8) * N + c) = hi;
            }
        }
    }
};

struct Fused3_64 {
    const float* g;
    const float* hid;
    const float* ihw;
    const float* hhw;
    const float* candw;
    const float* hhcw;
    const float* ihb;
    const float* hhb;
    const float* candb;
    const float* hhcb;
    float* Cg;
    float* Ct1;
    float* Ct2;
    int K;
    __device__ __forceinline__ const float* aChunk(int r, int k) const {
        if (k < EDIM) return g + (size_t)r * EDIM + k;
        return hid + (size_t)r * HDIM + (k - EDIM);
    }
    __device__ __forceinline__ void copyB(float* bs, int n0, int k0, int tid) const {
#pragma unroll
        for (int i = 0; i < 4; i++) {
            int c = tid + i * 128;
            int k = c >> 4, np = (c & 15) << 2;
            int gk = k0 + k, gc = n0 + np;
            const float* src = ihw;
            int sz = 16;
            if (gc < 2048) {
                src = (gk < EDIM) ? ihw + (size_t)gk * 2048 + gc
                                  : hhw + (size_t)(gk - EDIM) * 2048 + gc;
            } else if (gc < 3072) {
                if (gk < EDIM) src = candw + (size_t)gk * HDIM + (gc - 2048);
                else sz = 0;
            } else {
                if (gk >= EDIM) src = hhcw + (size_t)(gk - EDIM) * HDIM + (gc - 3072);
                else sz = 0;
            }
            cpa16z(bs + k * 72 + np, src, sz);
        }
    }
    __device__ __forceinline__ void store(const float (&acc)[2][4][4], int m0, int n0,
                                          int tid) const {
        const int lane = tid & 31, wid = tid >> 5, wm = wid >> 1, wn = wid & 1;
        float* C;
        const float* b0p;
        const float* b1p;
        int N, cbase, sig;
        if (n0 < 2048) {
            C = Cg; N = 2048; cbase = n0; b0p = ihb; b1p = hhb; sig = 1;
        } else if (n0 < 3072) {
            C = Ct1; N = HDIM; cbase = n0 - 2048; b0p = candb; b1p = nullptr; sig = 0;
        } else {
            C = Ct2; N = HDIM; cbase = n0 - 3072; b0p = hhcb; b1p = nullptr; sig = 0;
        }
#pragma unroll
        for (int mi = 0; mi < 2; mi++) {
            int r = m0 + wm * 32 + mi * 16 + (lane >> 2);
#pragma unroll
            for (int ni = 0; ni < 4; ni++) {
                int c = cbase + wn * 32 + ni * 8 + (lane & 3) * 2;
                float bx = b0p[c], by = b0p[c + 1];
                if (b1p) { bx += b1p[c]; by += b1p[c + 1]; }
                float2 lo = make_float2(acc[mi][ni][0] + bx, acc[mi][ni][1] + by);
                float2 hi = make_float2(acc[mi][ni][2] + bx, acc[mi][ni][3] + by);
                if (sig) {
                    lo.x = 1.f / (1.f + expf(-lo.x));
                    lo.y = 1.f / (1.f + expf(-lo.y));
                    hi.x = 1.f / (1.f + expf(-hi.x));
                    hi.y = 1.f / (1.f + expf(-hi.y));
                }
                *(float2*)(C + (size_t)r * N + c) = lo;
                *(float2*)(C + (size_t)(r + 8) * N + c) = hi;
            }
        }
    }
};

// =====================================================================
// score_gemm: fp16 mma, 128x256 tile, 512 threads / 16 warps (32x64 each),
// K-tile 32, double-buffered cp.async. 4 warps/SMSP -> latency hiding.
//   Asm: u32[2][128][20] (encH)   Bsm: u32[2][16][264] (UwP)
// Epilogue: tanh(D + Wh + Ub) . vw -> per-nblock partials.
// =====================================================================
#define AH_ST (128 * 20)
#define BH_ST (16 * 264)
#define SMEMH ((2 * AH_ST + 2 * BH_ST) * 4)

__launch_bounds__(512, 1)
__global__ void score_gemm(const __half* __restrict__ encH,
                           const uint32_t* __restrict__ UwP,
                           const float* __restrict__ Wh,
                           const float* __restrict__ Ub,
                           const float* __restrict__ vw,
                           float* __restrict__ part) {
    extern __shared__ uint32_t dsm[];
    uint32_t* Asm = dsm;
    uint32_t* Bsm = dsm + 2 * AH_ST;

    const int tid = threadIdx.x;
    const int lane = tid & 31, wid = tid >> 5;  // 16 warps
    const int wm = wid & 3, wn = wid >> 2;      // 4 m-slices x 4 n-slices
    const int q = lane >> 2, t = lane & 3;
    const int m0 = blockIdx.y * 128;
    const int n0 = blockIdx.x * 256;

    float acc[2][8][4];
#pragma unroll
    for (int i = 0; i < 2; i++)
#pragma unroll
        for (int j = 0; j < 8; j++)
#pragma unroll
            for (int r = 0; r < 4; r++) acc[i][j][r] = 0.0f;

    auto copyA = [&](int st, int k0) {
        uint32_t* ab = Asm + st * AH_ST;
        int row = tid >> 2, c8 = tid & 3;  // 512 chunks exactly
        cpa16(ab + row * 20 + c8 * 4, encH + (size_t)(m0 + row) * HDIM + k0 + c8 * 8);
    };
    auto copyB = [&](int st, int k0) {
        uint32_t* bb = Bsm + st * BH_ST;
        const int k20 = k0 >> 1;
#pragma unroll
        for (int i = 0; i < 2; i++) {
            int idx = tid + i * 512;  // 1024 chunks
            int k2 = idx >> 6, np = (idx & 63) << 2;
            cpa16(bb + k2 * 264 + np, UwP + (size_t)(k20 + k2) * HDIM + n0 + np);
        }
    };

    const int KT = HDIM >> 5;
    copyA(0, 0);
    copyB(0, 0);
    cpa_commit();
    copyA(1, 32);
    copyB(1, 32);
    cpa_commit();

    for (int kt = 0; kt < KT; kt++) {
        cpa_wait1();
        __syncthreads();
        const int st = kt & 1;
        const uint32_t* ab = Asm + st * AH_ST;
        const uint32_t* bb = Bsm + st * BH_ST;

#pragma unroll
        for (int g = 0; g < 2; g++) {
            const int o = g * 8;
            uint32_t af[2][4], bf[8][2];
#pragma unroll
            for (int ni = 0; ni < 8; ni++) {
                int nc = wn * 64 + ni * 8 + q;
                bf[ni][0] = bb[(o + t) * 264 + nc];
                bf[ni][1] = bb[(o + t + 4) * 264 + nc];
            }
#pragma unroll
            for (int mi = 0; mi < 2; mi++) {
                int mr = wm * 32 + mi * 16 + q;
                af[mi][0] = ab[mr * 20 + o + t];
                af[mi][1] = ab[(mr + 8) * 20 + o + t];
                af[mi][2] = ab[mr * 20 + o + t + 4];
                af[mi][3] = ab[(mr + 8) * 20 + o + t + 4];
            }
#pragma unroll
            for (int mi = 0; mi < 2; mi++)
#pragma unroll
                for (int ni = 0; ni < 8; ni++) mma16(acc[mi][ni], af[mi], bf[ni]);
        }
        __syncthreads();
        if (kt + 2 < KT) {
            copyA(st, (kt + 2) * 32);
            copyB(st, (kt + 2) * 32);
        }
        cpa_commit();
    }

    // ---- epilogue: tanh(D + Wh + Ub) . vw -> per-row partial ----
    float* red = (float*)dsm;  // [4][128]
    __syncthreads();
#pragma unroll
    for (int mi = 0; mi < 2; mi++) {
        int rl = wm * 32 + mi * 16 + q;
        int r0 = m0 + rl;
        const float* wh0 = Wh + (size_t)(r0 & (BATCH - 1)) * HDIM;
        const float* wh1 = Wh + (size_t)((r0 + 8) & (BATCH - 1)) * HDIM;
        float s0 = 0.f, s1 = 0.f;
#pragma unroll
        for (int ni = 0; ni < 8; ni++) {
            int c = n0 + wn * 64 + ni * 8 + t * 2;
            float u0 = Ub[c], u1 = Ub[c + 1];
            float w0 = vw[c], w1 = vw[c + 1];
            s0 += tanhf(acc[mi][ni][0] + wh0[c] + u0) * w0;
            s0 += tanhf(acc[mi][ni][1] + wh0[c + 1] + u1) * w1;
            s1 += tanhf(acc[mi][ni][2] + wh1[c] + u0) * w0;
            s1 += tanhf(acc[mi][ni][3] + wh1[c + 1] + u1) * w1;
        }
        s0 += __shfl_xor_sync(0xffffffffu, s0, 1);
        s0 += __shfl_xor_sync(0xffffffffu, s0, 2);
        s1 += __shfl_xor_sync(0xffffffffu, s1, 1);
        s1 += __shfl_xor_sync(0xffffffffu, s1, 2);
        if (t == 0) {
            red[wn * 128 + rl] = s0;
            red[wn * 128 + rl + 8] = s1;
        }
    }
    __syncthreads();
    if (tid < 128)
        part[(size_t)(n0 >> 8) * NSCORE + m0 + tid] =
            red[tid] + red[128 + tid] + red[256 + tid] + red[384 + tid];
}

// =====================================================================
// out2_gemm: fp16 mma, 128x256 tile, 512 threads / 16 warps (32x64 each),
// B staged as RAW fp32 via 4-BYTE cp.async (odd stride), in-reg cvt.
// Epilogue: logits + per-block row max / sumexp partials.
// =====================================================================
#define BO_ST (32 * 260)
#define SMEMO ((2 * AH_ST + 2 * BO_ST) * 4)

__launch_bounds__(512, 1)
__global__ void out2_gemm(const __half* __restrict__ AH,
                          const float* __restrict__ B,
                          const float* __restrict__ bias,
                          float* __restrict__ C,
                          float* __restrict__ lmax,
                          float* __restrict__ lsum) {
    extern __shared__ uint32_t dsm[];
    uint32_t* Asm = dsm;                    // [2][AH_ST]
    float* Bf = (float*)(dsm + 2 * AH_ST);  // [2][BO_ST]

    const int tid = threadIdx.x;
    const int lane = tid & 31, wid = tid >> 5;
    const int wm = wid & 3, wn = wid >> 2;
    const int q = lane >> 2, t = lane & 3;
    const int m0 = blockIdx.x * 128;  // m fastest
    const int n0 = blockIdx.y * 256;
    const int nb = blockIdx.y;

    float acc[2][8][4];
#pragma unroll
    for (int i = 0; i < 2; i++)
#pragma unroll
        for (int j = 0; j < 8; j++)
#pragma unroll
            for (int r = 0; r < 4; r++) acc[i][j][r] = 0.0f;

    auto copyA = [&](int st, int k0) {
        uint32_t* ab = Asm + st * AH_ST;
        int row = tid >> 2, c8 = tid & 3;
        cpa16(ab + row * 20 + c8 * 4, AH + (size_t)(m0 + row) * HDIM + k0 + c8 * 8);
    };
    auto copyB = [&](int st, int k0) {
        float* bb = Bf + st * BO_ST;
#pragma unroll
        for (int i = 0; i < 16; i++) {
            int idx = tid + i * 512;  // 8192 words: 32 k-rows x 256
            int k = idx >> 8, n = idx & 255;
            int gn = n0 + n;
            int ok = gn < VDIM;
            const float* src = B + (size_t)(k0 + k) * VDIM + (ok ? gn : 0);
            cpa4z(bb + k * 260 + n, src, ok ? 4 : 0);
        }
    };

    const int KT = HDIM >> 5;
    copyA(0, 0);
    copyB(0, 0);
    cpa_commit();
    copyA(1, 32);
    copyB(1, 32);
    cpa_commit();

    for (int kt = 0; kt < KT; kt++) {
        cpa_wait1();
        __syncthreads();
        const int st = kt & 1;
        const uint32_t* ab = Asm + st * AH_ST;
        const float* bb = Bf + st * BO_ST;

#pragma unroll
        for (int g = 0; g < 2; g++) {  // two k16 groups
            const int o = g * 16;      // fp32 row base
            uint32_t af[2][4], bf[8][2];
#pragma unroll
            for (int ni = 0; ni < 8; ni++) {
                int nc = wn * 64 + ni * 8 + q;
                bf[ni][0] = pack_h2(bb[(o + 2 * t) * 260 + nc],
                                    bb[(o + 2 * t + 1) * 260 + nc]);
                bf[ni][1] = pack_h2(bb[(o + 2 * t + 8) * 260 + nc],
                                    bb[(o + 2 * t + 9) * 260 + nc]);
            }
#pragma unroll
            for (int mi = 0; mi < 2; mi++) {
                int mr = wm * 32 + mi * 16 + q;
                af[mi][0] = ab[mr * 20 + g * 8 + t];
                af[mi][1] = ab[(mr + 8) * 20 + g * 8 + t];
                af[mi][2] = ab[mr * 20 + g * 8 + t + 4];
                af[mi][3] = ab[(mr + 8) * 20 + g * 8 + t + 4];
            }
#pragma unroll
            for (int mi = 0; mi < 2; mi++)
#pragma unroll
                for (int ni = 0; ni < 8; ni++) mma16(acc[mi][ni], af[mi], bf[ni]);
        }
        __syncthreads();
        if (kt + 2 < KT) {
            copyA(st, (kt + 2) * 32);
            copyB(st, (kt + 2) * 32);
        }
        cpa_commit();
    }

    // ---- epilogue: store logits + block-row max / sumexp ----
    __syncthreads();
    float* redm = (float*)dsm;  // [4][128]
    float* bmax = redm + 512;   // [128]

#pragma unroll
    for (int mi = 0; mi < 2; mi++) {
#pragma unroll
        for (int half = 0; half < 2; half++) {
            int rl = wm * 32 + mi * 16 + q + half * 8;
            int r = m0 + rl;
            float mx = -3.4e38f;
#pragma unroll
            for (int ni = 0; ni < 8; ni++) {
                int c0 = n0 + wn * 64 + ni * 8 + t * 2;
                if (c0 < VDIM) {
                    float v0 = acc[mi][ni][half * 2 + 0] + bias[c0];
                    C[(size_t)r * VDIM + c0] = v0;
                    mx = fmaxf(mx, v0);
                }
                if (c0 + 1 < VDIM) {
                    float v1 = acc[mi][ni][half * 2 + 1] + bias[c0 + 1];
                    C[(size_t)r * VDIM + c0 + 1] = v1;
                    mx = fmaxf(mx, v1);
                }
            }
            mx = fmaxf(mx, __shfl_xor_sync(0xffffffffu, mx, 1));
            mx = fmaxf(mx, __shfl_xor_sync(0xffffffffu, mx, 2));
            if (t == 0) redm[wn * 128 + rl] = mx;
        }
    }
    __syncthreads();
    if (tid < 128)
        bmax[tid] = fmaxf(fmaxf(redm[tid], redm[128 + tid]),
                          fmaxf(redm[256 + tid], redm[384 + tid]));
    __syncthreads();

#pragma unroll
    for (int mi = 0; mi < 2; mi++) {
#pragma unroll
        for (int half = 0; half < 2; half++) {
            int rl = wm * 32 + mi * 16 + q + half * 8;
            float bm = bmax[rl];
            float s = 0.f;
#pragma unroll
            for (int ni = 0; ni < 8; ni++) {
                int c0 = n0 + wn * 64 + ni * 8 + t * 2;
                if (c0 < VDIM) s += expf(acc[mi][ni][half * 2 + 0] + bias[c0] - bm);
                if (c0 + 1 < VDIM)
                    s += expf(acc[mi][ni][half * 2 + 1] + bias[c0 + 1] - bm);
            }
            s += __shfl_xor_sync(0xffffffffu, s, 1);
            s += __shfl_xor_sync(0xffffffffu, s, 2);
            if (t == 0) redm[wn * 128 + rl] = s;
        }
    }
    __syncthreads();
    if (tid < 128) {
        lmax[(size_t)nb * BATCH + m0 + tid] = bmax[tid];
        lsum[(size_t)nb * BATCH + m0 + tid] =
            redm[tid] + redm[128 + tid] + redm[256 + tid] + redm[384 + tid];
    }
}

// ---------------- fused softmax(S) + context (reads fp16 enc) ----------------
__global__ void softmax_ctx_kernel(const float* __restrict__ part,
                                   const __half* __restrict__ encH,
                                   float* __restrict__ attn_out,
                                   float* __restrict__ ctx) {
    const int n = blockIdx.x;
    const int tid = threadIdx.x;  // 256
    __shared__ float a[SDIM];
    __shared__ float rmax[4], rsum[4];

    float v = 0.f, e = 0.f;
    if (tid < SDIM) {
        const int idx = tid * BATCH + n;
        v = part[idx] + part[NSCORE + idx] + part[2 * NSCORE + idx] +
            part[3 * NSCORE + idx];
        float m = warp_max(v);
        if ((tid & 31) == 0) rmax[tid >> 5] = m;
    }
    __syncthreads();
    if (tid < SDIM) {
        float m = fmaxf(fmaxf(rmax[0], rmax[1]), fmaxf(rmax[2], rmax[3]));
        e = expf(v - m);
        float s = warp_sum(e);
        if ((tid & 31) == 0) rsum[tid >> 5] = s;
    }
    __syncthreads();
    if (tid < SDIM) {
        float sum = rsum[0] + rsum[1] + rsum[2] + rsum[3];
        float av = e / sum;
        attn_out[tid * BATCH + n] = av;
        a[tid] = av;
    }
    __syncthreads();

    float4 acc = make_float4(0.f, 0.f, 0.f, 0.f);
    for (int s = 0; s < SDIM; s++) {
        const __half2* ep =
            (const __half2*)(encH + ((size_t)s * BATCH + n) * HDIM) + tid * 2;
        float2 f0 = __half22float2(ep[0]);
        float2 f1 = __half22float2(ep[1]);
        float w = a[s];
        acc.x = fmaf(w, f0.x, acc.x);
        acc.y = fmaf(w, f0.y, acc.y);
        acc.z = fmaf(w, f1.x, acc.z);
        acc.w = fmaf(w, f1.y, acc.w);
    }
    ((float4*)(ctx + (size_t)n * HDIM))[tid] = acc;
}

// ---------------- GRU combine + LayerNorm ----------------
__global__ void fuse_hln_kernel(const float* __restrict__ gates,
                                const float* __restrict__ t1,
                                const float* __restrict__ t2,
                                const float* __restrict__ hid,
                                const float* __restrict__ lng,
                                const float* __restrict__ lnb,
                                float* __restrict__ hout) {
    const int n = blockIdx.x;
    const int tid = threadIdx.x;  // 256
    float4 z = ((const float4*)(gates + (size_t)n * 2 * HDIM))[tid];
    float4 r = ((const float4*)(gates + (size_t)n * 2 * HDIM + HDIM))[tid];
    float4 a = ((const float4*)(t1 + (size_t)n * HDIM))[tid];
    float4 b = ((const float4*)(t2 + (size_t)n * HDIM))[tid];
    float4 hv = ((const float4*)(hid + (size_t)n * HDIM))[tid];
    float4 hr;
    hr.x = (1.0f - z.x) * hv.x + z.x * tanhf(a.x + r.x * b.x);
    hr.y = (1.0f - z.y) * hv.y + z.y * tanhf(a.y + r.y * b.y);
    hr.z = (1.0f - z.z) * hv.z + z.z * tanhf(a.z + r.z * b.z);
    hr.w = (1.0f - z.w) * hv.w + z.w * tanhf(a.w + r.w * b.w);
    float s = hr.x + hr.y + hr.z + hr.w;
    float ss = hr.x * hr.x + hr.y * hr.y + hr.z * hr.z + hr.w * hr.w;
    __shared__ float sm1[8], sm2[8];
    float w1 = warp_sum(s), w2 = warp_sum(ss);
    if ((tid & 31) == 0) { sm1[tid >> 5] = w1; sm2[tid >> 5] = w2; }
    __syncthreads();
    float tot1 = 0.f, tot2 = 0.f;
#pragma unroll
    for (int qq = 0; qq < 8; qq++) { tot1 += sm1[qq]; tot2 += sm2[qq]; }
    float mu = tot1 * (1.0f / HDIM);
    float var = tot2 * (1.0f / HDIM) - mu * mu;
    float inv = rsqrtf(var + 1e-5f);
    float4 gg = ((const float4*)lng)[tid];
    float4 bb = ((const float4*)lnb)[tid];
    float4 o;
    o.x = (hr.x - mu) * inv * gg.x + bb.x;
    o.y = (hr.y - mu) * inv * gg.y + bb.y;
    o.z = (hr.z - mu) * inv * gg.z + bb.z;
    o.w = (hr.w - mu) * inv * gg.w + bb.w;
    ((float4*)(hout + (size_t)n * HDIM))[tid] = o;
}

// ---------------- final log_softmax: reduce partials + single RW pass ---------
__global__ void logsoftmax2_kernel(float* __restrict__ logits,
                                   const float* __restrict__ lmax,
                                   const float* __restrict__ lsum) {
    const int n = blockIdx.x;
    const int tid = threadIdx.x;  // 512
    __shared__ float sm[16];

    float m = -3.4e38f;
    for (int i = tid; i < NB2; i += 512) m = fmaxf(m, lmax[(size_t)i * BATCH + n]);
    m = warp_max(m);
    if ((tid & 31) == 0) sm[tid >> 5] = m;
    __syncthreads();
    float gmax = -3.4e38f;
#pragma unroll
    for (int qq = 0; qq < 16; qq++) gmax = fmaxf(gmax, sm[qq]);
    __syncthreads();

    float s = 0.f;
    for (int i = tid; i < NB2; i += 512)
        s += lsum[(size_t)i * BATCH + n] * expf(lmax[(size_t)i * BATCH + n] - gmax);
    s = warp_sum(s);
    if ((tid & 31) == 0) sm[tid >> 5] = s;
    __syncthreads();
    float tot = 0.f;
#pragma unroll
    for (int qq = 0; qq < 16; qq++) tot += sm[qq];
    float lse = gmax + logf(tot);

    float* row = logits + (size_t)n * VDIM;
    for (int i = tid; i < VDIM; i += 512) row[i] -= lse;
}

// ---------------- launch ----------------
extern "C" void kernel_launch(void* const* d_in, const int* in_sizes, int n_in,
                              void* d_out, int out_size) {
    const int* ids = (const int*)d_in[0];
    const float* hidden = (const float*)d_in[1];
    const float* enc = (const float*)d_in[2];
    const float* emb = (const float*)d_in[3];
    const float* W_w = (const float*)d_in[4];
    const float* W_b = (const float*)d_in[5];
    const float* U_w = (const float*)d_in[6];
    const float* U_b = (const float*)d_in[7];
    const float* v_w = (const float*)d_in[8];
    // d_in[9] = v_b : constant over S, cancels in softmax
    const float* ih_w = (const float*)d_in[10];
    const float* ih_b = (const float*)d_in[11];
    const float* hh_w = (const float*)d_in[12];
    const float* hh_b = (const float*)d_in[13];
    const float* cand_w = (const float*)d_in[14];
    const float* cand_b = (const float*)d_in[15];
    const float* hhc_w = (const float*)d_in[16];
    const float* hhc_b = (const float*)d_in[17];
    const float* comb_w = (const float*)d_in[18];
    const float* comb_b = (const float*)d_in[19];
    const float* ln_g = (const float*)d_in[20];
    const float* ln_b = (const float*)d_in[21];
    const float* out1_w = (const float*)d_in[22];
    const float* out1_b = (const float*)d_in[23];
    const float* out2_w = (const float*)d_in[24];
    const float* out2_b = (const float*)d_in[25];

    float* out_logits = (float*)d_out;
    float* out_h = out_logits + (size_t)BATCH * VDIM;
    float* out_attn = out_h + (size_t)BATCH * HDIM;

    float *Wh, *score4, *ctx, *gbuf, *gates, *t1, *t2, *lmax, *lsum;
    __half *encH, *o1h;
    uint32_t* UwP;
    cudaGetSymbolAddress((void**)&Wh, g_Wh);
    cudaGetSymbolAddress((void**)&score4, g_score4);
    cudaGetSymbolAddress((void**)&ctx, g_ctx);
    cudaGetSymbolAddress((void**)&gbuf, g_g);
    cudaGetSymbolAddress((void**)&gates, g_gates);
    cudaGetSymbolAddress((void**)&t1, g_t1);
    cudaGetSymbolAddress((void**)&t2, g_t2);
    cudaGetSymbolAddress((void**)&encH, g_encH);
    cudaGetSymbolAddress((void**)&o1h, g_o1h);
    cudaGetSymbolAddress((void**)&UwP, g_UwP);
    cudaGetSymbolAddress((void**)&lmax, g_lmax);
    cudaGetSymbolAddress((void**)&lsum, g_lsum);

    cudaFuncSetAttribute(score_gemm, cudaFuncAttributeMaxDynamicSharedMemorySize,
                         SMEMH);
    cudaFuncSetAttribute(out2_gemm, cudaFuncAttributeMaxDynamicSharedMemorySize,
                         SMEMO);
    cudaFuncSetAttribute(tgemm64<Plain64>,
                         cudaFuncAttributeMaxDynamicSharedMemorySize, SM64);
    cudaFuncSetAttribute(tgemm64<Plain64H>,
                         cudaFuncAttributeMaxDynamicSharedMemorySize, SM64);
    cudaFuncSetAttribute(tgemm64<Comb64>,
                         cudaFuncAttributeMaxDynamicSharedMemorySize, SM64);
    cudaFuncSetAttribute(tgemm64<Fused3_64>,
                         cudaFuncAttributeMaxDynamicSharedMemorySize, SM64);

    // 0. conversions
    f2h_kernel<<<(SDIM * BATCH * HDIM) / 1024, 256>>>(enc, encH, SDIM * BATCH * HDIM);
    packb_kernel<<<dim3(HDIM / 256, HDIM / 2), 256>>>(U_w, UwP, HDIM, HDIM);

    // 1. Wh = hidden @ W_w + W_b
    {
        Plain64 p{hidden, W_w, W_b, Wh, HDIM, HDIM, 0};
        tgemm64<Plain64><<<dim3(HDIM / 64, BATCH / 64), 128, SM64>>>(p);
    }
    // 2. fused score GEMM (512 threads) -> 4 partial buffers
    score_gemm<<<dim3(HDIM / 256, (SDIM * BATCH) / 128), 512, SMEMH>>>(
        encH, UwP, Wh, U_b, v_w, score4);
    // 3. fused softmax + context (fp16 enc)
    softmax_ctx_kernel<<<BATCH, 256>>>(score4, encH, out_attn, ctx);
    // 4. g = relu([emb[ids], ctx] @ comb_w + comb_b)
    {
        Comb64 p{emb, ids, ctx, comb_w, comb_b, gbuf, EDIM + HDIM};
        tgemm64<Comb64><<<dim3(EDIM / 64, BATCH / 64), 128, SM64>>>(p);
    }
    // 5. fused gates | t1 | t2
    {
        Fused3_64 p{gbuf, hidden, ih_w, hh_w, cand_w, hhc_w,
                    ih_b, hh_b, cand_b, hhc_b, gates, t1, t2, EDIM + HDIM};
        tgemm64<Fused3_64><<<dim3(4096 / 64, BATCH / 64), 128, SM64>>>(p);
    }
    // 6. GRU combine + LayerNorm
    fuse_hln_kernel<<<BATCH, 256>>>(gates, t1, t2, hidden, ln_g, ln_b, out_h);
    // 7. o1h = relu(h @ out1_w + out1_b) directly in fp16
    {
        Plain64H p{out_h, out1_w, out1_b, o1h, HDIM, HDIM};
        tgemm64<Plain64H><<<dim3(HDIM / 64, BATCH / 64), 128, SM64>>>(p);
    }
    // 8. logits + fused log-softmax partials (512 threads)
    out2_gemm<<<dim3(BATCH / 128, NB2), 512, SMEMO>>>(o1h, out2_w, out2_b, out_logits,
                                                      lmax, lsum);
    // 9. final log_softmax: reduce partials + single pass
    logsoftmax2_kernel<<<BATCH, 512>>>(out_logits, lmax, lsum);
}

// round 17
// speedup vs baseline: 1.1293x; 1.0172x over previous
#include <cuda_runtime.h>
#include <cuda_fp16.h>
#include <cstdint>

#define BATCH 256
#define HDIM  1024
#define EDIM  512
#define SDIM  128
#define VDIM  50257
#define NSCORE (SDIM * BATCH)
#define NB2 ((VDIM + 255) / 256)  // 197 out2 n-blocks

// ---------------- scratch (no allocations allowed) ----------------
__device__ float g_Wh[BATCH * HDIM];
__device__ float g_score4[4 * NSCORE];  // per-nblock score partials
__device__ float g_ctx[BATCH * HDIM];
__device__ float g_g[BATCH * EDIM];
__device__ float g_gates[BATCH * 2 * HDIM];
__device__ float g_t1[BATCH * HDIM];
__device__ float g_t2[BATCH * HDIM];
__device__ __half g_encH[SDIM * BATCH * HDIM];  // enc as fp16
__device__ __half g_o1h[BATCH * HDIM];          // o1 as fp16
__device__ uint32_t g_UwP[(HDIM / 2) * HDIM];   // U_w k-pair packed fp16
__device__ float g_lmax[NB2 * BATCH];           // out2 per-block row max
__device__ float g_lsum[NB2 * BATCH];           // out2 per-block row sumexp

// ---------------- helpers ----------------
__device__ __forceinline__ float warp_sum(float v) {
#pragma unroll
    for (int o = 16; o > 0; o >>= 1) v += __shfl_xor_sync(0xffffffffu, v, o);
    return v;
}
__device__ __forceinline__ float warp_max(float v) {
#pragma unroll
    for (int o = 16; o > 0; o >>= 1) v = fmaxf(v, __shfl_xor_sync(0xffffffffu, v, o));
    return v;
}

__device__ __forceinline__ void mma8(float* c, const uint32_t* a, const uint32_t* b) {
    asm volatile(
        "mma.sync.aligned.m16n8k8.row.col.f32.tf32.tf32.f32 "
        "{%0,%1,%2,%3}, {%4,%5,%6,%7}, {%8,%9}, {%0,%1,%2,%3};"
        : "+f"(c[0]), "+f"(c[1]), "+f"(c[2]), "+f"(c[3])
        : "r"(a[0]), "r"(a[1]), "r"(a[2]), "r"(a[3]), "r"(b[0]), "r"(b[1]));
}
__device__ __forceinline__ void mma16(float* c, const uint32_t* a, const uint32_t* b) {
    asm volatile(
        "mma.sync.aligned.m16n8k16.row.col.f32.f16.f16.f32 "
        "{%0,%1,%2,%3}, {%4,%5,%6,%7}, {%8,%9}, {%0,%1,%2,%3};"
        : "+f"(c[0]), "+f"(c[1]), "+f"(c[2]), "+f"(c[3])
        : "r"(a[0]), "r"(a[1]), "r"(a[2]), "r"(a[3]), "r"(b[0]), "r"(b[1]));
}

// ldmatrix x4: loads 4 8x8 b16 matrices; lane l supplies row address for
// matrix l>>3, row l&7.
__device__ __forceinline__ void ldsm4(uint32_t* r, uint32_t smem_addr) {
    asm volatile(
        "ldmatrix.sync.aligned.m8n8.x4.shared.b16 {%0,%1,%2,%3}, [%4];"
        : "=r"(r[0]), "=r"(r[1]), "=r"(r[2]), "=r"(r[3])
        : "r"(smem_addr));
}

__device__ __forceinline__ void cpa16(void* smem_dst, const void* gsrc) {
    uint32_t d = (uint32_t)__cvta_generic_to_shared(smem_dst);
    asm volatile("cp.async.ca.shared.global [%0], [%1], 16;" ::"r"(d), "l"(gsrc));
}
__device__ __forceinline__ void cpa16z(void* smem_dst, const void* gsrc, int srcsz) {
    uint32_t d = (uint32_t)__cvta_generic_to_shared(smem_dst);
    asm volatile("cp.async.ca.shared.global [%0], [%1], 16, %2;" ::"r"(d), "l"(gsrc),
                 "r"(srcsz));
}
__device__ __forceinline__ void cpa4z(void* smem_dst, const void* gsrc, int srcsz) {
    uint32_t d = (uint32_t)__cvta_generic_to_shared(smem_dst);
    asm volatile("cp.async.ca.shared.global [%0], [%1], 4, %2;" ::"r"(d), "l"(gsrc),
                 "r"(srcsz));
}
__device__ __forceinline__ void cpa_commit() {
    asm volatile("cp.async.commit_group;");
}
__device__ __forceinline__ void cpa_wait1() {
    asm volatile("cp.async.wait_group 1;");
}

__device__ __forceinline__ uint32_t pack_h2(float a, float b) {
    __half2 h = __floats2half2_rn(a, b);
    return *(uint32_t*)&h;
}

// fp32 -> fp16, n multiple of 4
__global__ void f2h_kernel(const float* __restrict__ src, __half* __restrict__ dst,
                           int n) {
    int i = (blockIdx.x * blockDim.x + threadIdx.x) * 4;
    if (i < n) {
        float4 v = *(const float4*)(src + i);
        __half2 h0 = __floats2half2_rn(v.x, v.y);
        __half2 h1 = __floats2half2_rn(v.z, v.w);
        *(__half2*)(dst + i) = h0;
        *(__half2*)(dst + i + 2) = h1;
    }
}

// pack B[k][n] fp32 (row stride N) -> BP[k/2][n] u32 (row stride NP)
__global__ void packb_kernel(const float* __restrict__ B, uint32_t* __restrict__ BP,
                             int N, int NP) {
    int n = blockIdx.x * blockDim.x + threadIdx.x;
    int k2 = blockIdx.y;
    if (n < NP) {
        uint32_t out = 0;
        if (n < N)
            out = pack_h2(B[(size_t)(2 * k2) * N + n], B[(size_t)(2 * k2 + 1) * N + n]);
        BP[(size_t)k2 * NP + n] = out;
    }
}

// =====================================================================
// tgemm64: tf32, 64x64 tile, 128 threads (4 warps of 32x32), K-tile 32,
// 3-stage cp.async pipeline. Dynamic smem.
// =====================================================================
#define SM64 ((3 * 64 * 36 + 3 * 32 * 72) * 4)

template <class P>
__launch_bounds__(128)
__global__ void tgemm64(P p) {
    extern __shared__ float dsm64[];
    float(*As)[64][36] = (float(*)[64][36])dsm64;
    float(*Bs)[32][72] = (float(*)[32][72])(dsm64 + 3 * 64 * 36);

    const int tid = threadIdx.x;
    const int lane = tid & 31, wid = tid >> 5;
    const int wm = wid >> 1, wn = wid & 1;
    const int q = lane >> 2, t = lane & 3;
    const int m0 = blockIdx.y * 64;
    const int n0 = blockIdx.x * 64;

    float acc[2][4][4];
#pragma unroll
    for (int i = 0; i < 2; i++)
#pragma unroll
        for (int j = 0; j < 4; j++)
#pragma unroll
            for (int r = 0; r < 4; r++) acc[i][j][r] = 0.0f;

    auto fill = [&](int st, int k0) {
#pragma unroll
        for (int i = 0; i < 4; i++) {
            int c = tid + i * 128;
            int row = c >> 3, kp = (c & 7) << 2;
            cpa16(&As[st][row][kp], p.aChunk(m0 + row, k0 + kp));
        }
        p.copyB(&Bs[st][0][0], n0, k0, tid);
    };

    const int KT = p.K >> 5;
    fill(0, 0);
    cpa_commit();
    fill(1, 32);
    cpa_commit();

    for (int kt = 0; kt < KT; kt++) {
        cpa_wait1();
        __syncthreads();
        if (kt + 2 < KT) fill((kt + 2) % 3, (kt + 2) * 32);
        cpa_commit();
        const int st = kt % 3;

#pragma unroll
        for (int k8 = 0; k8 < 32; k8 += 8) {
            uint32_t af[2][4], bf[4][2];
#pragma unroll
            for (int ni = 0; ni < 4; ni++) {
                int nc = wn * 32 + ni * 8 + q;
                bf[ni][0] = __float_as_uint(Bs[st][k8 + t][nc]);
                bf[ni][1] = __float_as_uint(Bs[st][k8 + t + 4][nc]);
            }
#pragma unroll
            for (int mi = 0; mi < 2; mi++) {
                int mr = wm * 32 + mi * 16 + q;
                af[mi][0] = __float_as_uint(As[st][mr][k8 + t]);
                af[mi][1] = __float_as_uint(As[st][mr + 8][k8 + t]);
                af[mi][2] = __float_as_uint(As[st][mr][k8 + t + 4]);
                af[mi][3] = __float_as_uint(As[st][mr + 8][k8 + t + 4]);
            }
#pragma unroll
            for (int mi = 0; mi < 2; mi++)
#pragma unroll
                for (int ni = 0; ni < 4; ni++) mma8(acc[mi][ni], af[mi], bf[ni]);
        }
    }
    __syncthreads();
    p.store(acc, m0, n0, tid);
}

__device__ __forceinline__ void copyB64_dense(float* bs, const float* B, int ldb,
                                              int n0, int k0, int tid) {
#pragma unroll
    for (int i = 0; i < 4; i++) {
        int c = tid + i * 128;
        int k = c >> 4, np = (c & 15) << 2;
        cpa16(bs + k * 72 + np, B + (size_t)(k0 + k) * ldb + n0 + np);
    }
}

// ---------------- tgemm64 functors ----------------
struct Plain64 {
    const float* A;
    const float* B;
    const float* bias;
    float* C;
    int K;
    int N;
    int act;  // 0=none, 1=relu
    __device__ __forceinline__ const float* aChunk(int r, int k) const {
        return A + (size_t)r * K + k;
    }
    __device__ __forceinline__ void copyB(float* bs, int n0, int k0, int tid) const {
        copyB64_dense(bs, B, N, n0, k0, tid);
    }
    __device__ __forceinline__ void store(const float (&acc)[2][4][4], int m0, int n0,
                                          int tid) const {
        const int lane = tid & 31, wid = tid >> 5, wm = wid >> 1, wn = wid & 1;
#pragma unroll
        for (int mi = 0; mi < 2; mi++) {
            int r = m0 + wm * 32 + mi * 16 + (lane >> 2);
#pragma unroll
            for (int ni = 0; ni < 4; ni++) {
                int c = n0 + wn * 32 + ni * 8 + (lane & 3) * 2;
                float bx = bias[c], by = bias[c + 1];
                float2 lo = make_float2(acc[mi][ni][0] + bx, acc[mi][ni][1] + by);
                float2 hi = make_float2(acc[mi][ni][2] + bx, acc[mi][ni][3] + by);
                if (act == 1) {
                    lo.x = fmaxf(lo.x, 0.f);
                    lo.y = fmaxf(lo.y, 0.f);
                    hi.x = fmaxf(hi.x, 0.f);
                    hi.y = fmaxf(hi.y, 0.f);
                }
                *(float2*)(C + (size_t)r * N + c) = lo;
                *(float2*)(C + (size_t)(r + 8) * N + c) = hi;
            }
        }
    }
};

// relu + fp16 output (o1 -> o1h directly)
struct Plain64H {
    const float* A;
    const float* B;
    const float* bias;
    __half* C;
    int K;
    int N;
    __device__ __forceinline__ const float* aChunk(int r, int k) const {
        return A + (size_t)r * K + k;
    }
    __device__ __forceinline__ void copyB(float* bs, int n0, int k0, int tid) const {
        copyB64_dense(bs, B, N, n0, k0, tid);
    }
    __device__ __forceinline__ void store(const float (&acc)[2][4][4], int m0, int n0,
                                          int tid) const {
        const int lane = tid & 31, wid = tid >> 5, wm = wid >> 1, wn = wid & 1;
#pragma unroll
        for (int mi = 0; mi < 2; mi++) {
            int r = m0 + wm * 32 + mi * 16 + (lane >> 2);
#pragma unroll
            for (int ni = 0; ni < 4; ni++) {
                int c = n0 + wn * 32 + ni * 8 + (lane & 3) * 2;
                float bx = bias[c], by = bias[c + 1];
                __half2 lo = __floats2half2_rn(fmaxf(acc[mi][ni][0] + bx, 0.f),
                                               fmaxf(acc[mi][ni][1] + by, 0.f));
                __half2 hi = __floats2half2_rn(fmaxf(acc[mi][ni][2] + bx, 0.f),
                                               fmaxf(acc[mi][ni][3] + by, 0.f));
                *(__half2*)(C + (size_t)r * N + c) = lo;
                *(__half2*)(C + (size_t)(r + 8) * N + c) = hi;
            }
        }
    }
};

struct Comb64 {
    const float* emb;
    const int* ids;
    const float* ctx;
    const float* B;
    const float* bias;
    float* C;
    int K;
    __device__ __forceinline__ const float* aChunk(int r, int k) const {
        if (k < EDIM) return emb + (size_t)__ldg(&ids[r]) * EDIM + k;
        return ctx + (size_t)r * HDIM + (k - EDIM);
    }
    __device__ __forceinline__ void copyB(float* bs, int n0, int k0, int tid) const {
        copyB64_dense(bs, B, EDIM, n0, k0, tid);
    }
    __device__ __forceinline__ void store(const float (&acc)[2][4][4], int m0, int n0,
                                          int tid) const {
        const int lane = tid & 31, wid = tid >> 5, wm = wid >> 1, wn = wid & 1;
        const int N = EDIM;
#pragma unroll
        for (int mi = 0; mi < 2; mi++) {
            int r = m0 + wm * 32 + mi * 16 + (lane >> 2);
#pragma unroll
            for (int ni = 0; ni < 4; ni++) {
                int c = n0 + wn * 32 + ni * 8 + (lane & 3) * 2;
                float bx = bias[c], by = bias[c + 1];
                float2 lo = make_float2(fmaxf(acc[mi][ni][0] + bx, 0.f),
                                        fmaxf(acc[mi][ni][1] + by, 0.f));
                float2 hi = make_float2(fmaxf(acc[mi][ni][2] + bx, 0.f),
                                        fmaxf(acc[mi][ni][3] + by, 0.f));
                *(float2*)(C + (size_t)r * N + c) = lo;
                *(float2*)(C + (size_t)(r + 8) * N + c) = hi;
            }
        }
    }
};

struct Fused3_64 {
    const float* g;
    const float* hid;
    const float* ihw;
    const float* hhw;
    const float* candw;
    const float* hhcw;
    const float* ihb;
    const float* hhb;
    const float* candb;
    const float* hhcb;
    float* Cg;
    float* Ct1;
    float* Ct2;
    int K;
    __device__ __forceinline__ const float* aChunk(int r, int k) const {
        if (k < EDIM) return g + (size_t)r * EDIM + k;
        return hid + (size_t)r * HDIM + (k - EDIM);
    }
    __device__ __forceinline__ void copyB(float* bs, int n0, int k0, int tid) const {
#pragma unroll
        for (int i = 0; i < 4; i++) {
            int c = tid + i * 128;
            int k = c >> 4, np = (c & 15) << 2;
            int gk = k0 + k, gc = n0 + np;
            const float* src = ihw;
            int sz = 16;
            if (gc < 2048) {
                src = (gk < EDIM) ? ihw + (size_t)gk * 2048 + gc
                                  : hhw + (size_t)(gk - EDIM) * 2048 + gc;
            } else if (gc < 3072) {
                if (gk < EDIM) src = candw + (size_t)gk * HDIM + (gc - 2048);
                else sz = 0;
            } else {
                if (gk >= EDIM) src = hhcw + (size_t)(gk - EDIM) * HDIM + (gc - 3072);
                else sz = 0;
            }
            cpa16z(bs + k * 72 + np, src, sz);
        }
    }
    __device__ __forceinline__ void store(const float (&acc)[2][4][4], int m0, int n0,
                                          int tid) const {
        const int lane = tid & 31, wid = tid >> 5, wm = wid >> 1, wn = wid & 1;
        float* C;
        const float* b0p;
        const float* b1p;
        int N, cbase, sig;
        if (n0 < 2048) {
            C = Cg; N = 2048; cbase = n0; b0p = ihb; b1p = hhb; sig = 1;
        } else if (n0 < 3072) {
            C = Ct1; N = HDIM; cbase = n0 - 2048; b0p = candb; b1p = nullptr; sig = 0;
        } else {
            C = Ct2; N = HDIM; cbase = n0 - 3072; b0p = hhcb; b1p = nullptr; sig = 0;
        }
#pragma unroll
        for (int mi = 0; mi < 2; mi++) {
            int r = m0 + wm * 32 + mi * 16 + (lane >> 2);
#pragma unroll
            for (int ni = 0; ni < 4; ni++) {
                int c = cbase + wn * 32 + ni * 8 + (lane & 3) * 2;
                float bx = b0p[c], by = b0p[c + 1];
                if (b1p) { bx += b1p[c]; by += b1p[c + 1]; }
                float2 lo = make_float2(acc[mi][ni][0] + bx, acc[mi][ni][1] + by);
                float2 hi = make_float2(acc[mi][ni][2] + bx, acc[mi][ni][3] + by);
                if (sig) {
                    lo.x = 1.f / (1.f + expf(-lo.x));
                    lo.y = 1.f / (1.f + expf(-lo.y));
                    hi.x = 1.f / (1.f + expf(-hi.x));
                    hi.y = 1.f / (1.f + expf(-hi.y));
                }
                *(float2*)(C + (size_t)r * N + c) = lo;
                *(float2*)(C + (size_t)(r + 8) * N + c) = hi;
            }
        }
    }
};

// =====================================================================
// score_gemm: fp16 mma, 128x256 tile, 512 threads / 16 warps (32x64 each),
// K-tile 32, double-buffered cp.async. A fragments via ldmatrix.x4.
//   Asm: u32[2][128][20] (encH)   Bsm: u32[2][16][264] (UwP)
// Epilogue: tanh(D + Wh + Ub) . vw -> per-nblock partials.
// =====================================================================
#define AH_ST (128 * 20)
#define BH_ST (16 * 264)
#define SMEMH ((2 * AH_ST + 2 * BH_ST) * 4)

__launch_bounds__(512, 1)
__global__ void score_gemm(const __half* __restrict__ encH,
                           const uint32_t* __restrict__ UwP,
                           const float* __restrict__ Wh,
                           const float* __restrict__ Ub,
                           const float* __restrict__ vw,
                           float* __restrict__ part) {
    extern __shared__ uint32_t dsm[];
    uint32_t* Asm = dsm;
    uint32_t* Bsm = dsm + 2 * AH_ST;

    const int tid = threadIdx.x;
    const int lane = tid & 31, wid = tid >> 5;  // 16 warps
    const int wm = wid & 3, wn = wid >> 2;      // 4 m-slices x 4 n-slices
    const int q = lane >> 2, t = lane & 3;
    const int m0 = blockIdx.y * 128;
    const int n0 = blockIdx.x * 256;

    // ldmatrix lane geometry: matrix = lane>>3
    const int lrow = (lane & 7) + ((lane >> 3) & 1) * 8;  // row within 16-row slab
    const int lcol = (lane >> 4) * 4;                     // u32 col offset (0 or 4)

    float acc[2][8][4];
#pragma unroll
    for (int i = 0; i < 2; i++)
#pragma unroll
        for (int j = 0; j < 8; j++)
#pragma unroll
            for (int r = 0; r < 4; r++) acc[i][j][r] = 0.0f;

    auto copyA = [&](int st, int k0) {
        uint32_t* ab = Asm + st * AH_ST;
        int row = tid >> 2, c8 = tid & 3;  // 512 chunks exactly
        cpa16(ab + row * 20 + c8 * 4, encH + (size_t)(m0 + row) * HDIM + k0 + c8 * 8);
    };
    auto copyB = [&](int st, int k0) {
        uint32_t* bb = Bsm + st * BH_ST;
        const int k20 = k0 >> 1;
#pragma unroll
        for (int i = 0; i < 2; i++) {
            int idx = tid + i * 512;  // 1024 chunks
            int k2 = idx >> 6, np = (idx & 63) << 2;
            cpa16(bb + k2 * 264 + np, UwP + (size_t)(k20 + k2) * HDIM + n0 + np);
        }
    };

    const int KT = HDIM >> 5;
    copyA(0, 0);
    copyB(0, 0);
    cpa_commit();
    copyA(1, 32);
    copyB(1, 32);
    cpa_commit();

    for (int kt = 0; kt < KT; kt++) {
        cpa_wait1();
        __syncthreads();
        const int st = kt & 1;
        const uint32_t* ab = Asm + st * AH_ST;
        const uint32_t* bb = Bsm + st * BH_ST;

#pragma unroll
        for (int g = 0; g < 2; g++) {
            const int o = g * 8;
            uint32_t af[2][4], bf[8][2];
#pragma unroll
            for (int ni = 0; ni < 8; ni++) {
                int nc = wn * 64 + ni * 8 + q;
                bf[ni][0] = bb[(o + t) * 264 + nc];
                bf[ni][1] = bb[(o + t + 4) * 264 + nc];
            }
#pragma unroll
            for (int mi = 0; mi < 2; mi++) {
                int mr = wm * 32 + mi * 16 + lrow;
                ldsm4(af[mi],
                      (uint32_t)__cvta_generic_to_shared(ab + mr * 20 + o + lcol));
            }
#pragma unroll
            for (int mi = 0; mi < 2; mi++)
#pragma unroll
                for (int ni = 0; ni < 8; ni++) mma16(acc[mi][ni], af[mi], bf[ni]);
        }
        __syncthreads();
        if (kt + 2 < KT) {
            copyA(st, (kt + 2) * 32);
            copyB(st, (kt + 2) * 32);
        }
        cpa_commit();
    }

    // ---- epilogue: tanh(D + Wh + Ub) . vw -> per-row partial ----
    float* red = (float*)dsm;  // [4][128]
    __syncthreads();
#pragma unroll
    for (int mi = 0; mi < 2; mi++) {
        int rl = wm * 32 + mi * 16 + q;
        int r0 = m0 + rl;
        const float* wh0 = Wh + (size_t)(r0 & (BATCH - 1)) * HDIM;
        const float* wh1 = Wh + (size_t)((r0 + 8) & (BATCH - 1)) * HDIM;
        float s0 = 0.f, s1 = 0.f;
#pragma unroll
        for (int ni = 0; ni < 8; ni++) {
            int c = n0 + wn * 64 + ni * 8 + t * 2;
            float u0 = Ub[c], u1 = Ub[c + 1];
            float w0 = vw[c], w1 = vw[c + 1];
            s0 += tanhf(acc[mi][ni][0] + wh0[c] + u0) * w0;
            s0 += tanhf(acc[mi][ni][1] + wh0[c + 1] + u1) * w1;
            s1 += tanhf(acc[mi][ni][2] + wh1[c] + u0) * w0;
            s1 += tanhf(acc[mi][ni][3] + wh1[c + 1] + u1) * w1;
        }
        s0 += __shfl_xor_sync(0xffffffffu, s0, 1);
        s0 += __shfl_xor_sync(0xffffffffu, s0, 2);
        s1 += __shfl_xor_sync(0xffffffffu, s1, 1);
        s1 += __shfl_xor_sync(0xffffffffu, s1, 2);
        if (t == 0) {
            red[wn * 128 + rl] = s0;
            red[wn * 128 + rl + 8] = s1;
        }
    }
    __syncthreads();
    if (tid < 128)
        part[(size_t)(n0 >> 8) * NSCORE + m0 + tid] =
            red[tid] + red[128 + tid] + red[256 + tid] + red[384 + tid];
}

// =====================================================================
// out2_gemm: fp16 mma, 128x256 tile, 512 threads / 16 warps (32x64 each),
// B staged as RAW fp32 via 4-BYTE cp.async (odd stride), in-reg cvt.
// A fragments via ldmatrix.x4. Epilogue: logits + row max/sumexp partials.
// =====================================================================
#define BO_ST (32 * 260)
#define SMEMO ((2 * AH_ST + 2 * BO_ST) * 4)

__launch_bounds__(512, 1)
__global__ void out2_gemm(const __half* __restrict__ AH,
                          const float* __restrict__ B,
                          const float* __restrict__ bias,
                          float* __restrict__ C,
                          float* __restrict__ lmax,
                          float* __restrict__ lsum) {
    extern __shared__ uint32_t dsm[];
    uint32_t* Asm = dsm;                    // [2][AH_ST]
    float* Bf = (float*)(dsm + 2 * AH_ST);  // [2][BO_ST]

    const int tid = threadIdx.x;
    const int lane = tid & 31, wid = tid >> 5;
    const int wm = wid & 3, wn = wid >> 2;
    const int q = lane >> 2, t = lane & 3;
    const int m0 = blockIdx.x * 128;  // m fastest
    const int n0 = blockIdx.y * 256;
    const int nb = blockIdx.y;

    const int lrow = (lane & 7) + ((lane >> 3) & 1) * 8;
    const int lcol = (lane >> 4) * 4;

    float acc[2][8][4];
#pragma unroll
    for (int i = 0; i < 2; i++)
#pragma unroll
        for (int j = 0; j < 8; j++)
#pragma unroll
            for (int r = 0; r < 4; r++) acc[i][j][r] = 0.0f;

    auto copyA = [&](int st, int k0) {
        uint32_t* ab = Asm + st * AH_ST;
        int row = tid >> 2, c8 = tid & 3;
        cpa16(ab + row * 20 + c8 * 4, AH + (size_t)(m0 + row) * HDIM + k0 + c8 * 8);
    };
    auto copyB = [&](int st, int k0) {
        float* bb = Bf + st * BO_ST;
#pragma unroll
        for (int i = 0; i < 16; i++) {
            int idx = tid + i * 512;  // 8192 words: 32 k-rows x 256
            int k = idx >> 8, n = idx & 255;
            int gn = n0 + n;
            int ok = gn < VDIM;
            const float* src = B + (size_t)(k0 + k) * VDIM + (ok ? gn : 0);
            cpa4z(bb + k * 260 + n, src, ok ? 4 : 0);
        }
    };

    const int KT = HDIM >> 5;
    copyA(0, 0);
    copyB(0, 0);
    cpa_commit();
    copyA(1, 32);
    copyB(1, 32);
    cpa_commit();

    for (int kt = 0; kt < KT; kt++) {
        cpa_wait1();
        __syncthreads();
        const int st = kt & 1;
        const uint32_t* ab = Asm + st * AH_ST;
        const float* bb = Bf + st * BO_ST;

#pragma unroll
        for (int g = 0; g < 2; g++) {  // two k16 groups
            const int o = g * 16;      // fp32 row base
            uint32_t af[2][4], bf[8][2];
#pragma unroll
            for (int ni = 0; ni < 8; ni++) {
                int nc = wn * 64 + ni * 8 + q;
                bf[ni][0] = pack_h2(bb[(o + 2 * t) * 260 + nc],
                                    bb[(o + 2 * t + 1) * 260 + nc]);
                bf[ni][1] = pack_h2(bb[(o + 2 * t + 8) * 260 + nc],
                                    bb[(o + 2 * t + 9) * 260 + nc]);
            }
#pragma unroll
            for (int mi = 0; mi < 2; mi++) {
                int mr = wm * 32 + mi * 16 + lrow;
                ldsm4(af[mi], (uint32_t)__cvta_generic_to_shared(ab + mr * 20 +
                                                                 g * 8 + lcol));
            }
#pragma unroll
            for (int mi = 0; mi < 2; mi++)
#pragma unroll
                for (int ni = 0; ni < 8; ni++) mma16(acc[mi][ni], af[mi], bf[ni]);
        }
        __syncthreads();
        if (kt + 2 < KT) {
            copyA(st, (kt + 2) * 32);
            copyB(st, (kt + 2) * 32);
        }
        cpa_commit();
    }

    // ---- epilogue: store logits + block-row max / sumexp ----
    __syncthreads();
    float* redm = (float*)dsm;  // [4][128]
    float* bmax = redm + 512;   // [128]

#pragma unroll
    for (int mi = 0; mi < 2; mi++) {
#pragma unroll
        for (int half = 0; half < 2; half++) {
            int rl = wm * 32 + mi * 16 + q + half * 8;
            int r = m0 + rl;
            float mx = -3.4e38f;
#pragma unroll
            for (int ni = 0; ni < 8; ni++) {
                int c0 = n0 + wn * 64 + ni * 8 + t * 2;
                if (c0 < VDIM) {
                    float v0 = acc[mi][ni][half * 2 + 0] + bias[c0];
                    C[(size_t)r * VDIM + c0] = v0;
                    mx = fmaxf(mx, v0);
                }
                if (c0 + 1 < VDIM) {
                    float v1 = acc[mi][ni][half * 2 + 1] + bias[c0 + 1];
                    C[(size_t)r * VDIM + c0 + 1] = v1;
                    mx = fmaxf(mx, v1);
                }
            }
            mx = fmaxf(mx, __shfl_xor_sync(0xffffffffu, mx, 1));
            mx = fmaxf(mx, __shfl_xor_sync(0xffffffffu, mx, 2));
            if (t == 0) redm[wn * 128 + rl] = mx;
        }
    }
    __syncthreads();
    if (tid < 128)
        bmax[tid] = fmaxf(fmaxf(redm[tid], redm[128 + tid]),
                          fmaxf(redm[256 + tid], redm[384 + tid]));
    __syncthreads();

#pragma unroll
    for (int mi = 0; mi < 2; mi++) {
#pragma unroll
        for (int half = 0; half < 2; half++) {
            int rl = wm * 32 + mi * 16 + q + half * 8;
            float bm = bmax[rl];
            float s = 0.f;
#pragma unroll
            for (int ni = 0; ni < 8; ni++) {
                int c0 = n0 + wn * 64 + ni * 8 + t * 2;
                if (c0 < VDIM) s += expf(acc[mi][ni][half * 2 + 0] + bias[c0] - bm);
                if (c0 + 1 < VDIM)
                    s += expf(acc[mi][ni][half * 2 + 1] + bias[c0 + 1] - bm);
            }
            s += __shfl_xor_sync(0xffffffffu, s, 1);
            s += __shfl_xor_sync(0xffffffffu, s, 2);
            if (t == 0) redm[wn * 128 + rl] = s;
        }
    }
    __syncthreads();
    if (tid < 128) {
        lmax[(size_t)nb * BATCH + m0 + tid] = bmax[tid];
        lsum[(size_t)nb * BATCH + m0 + tid] =
            redm[tid] + redm[128 + tid] + redm[256 + tid] + redm[384 + tid];
    }
}

// ---------------- fused softmax(S) + context (reads fp16 enc) ----------------
__global__ void softmax_ctx_kernel(const float* __restrict__ part,
                                   const __half* __restrict__ encH,
                                   float* __restrict__ attn_out,
                                   float* __restrict__ ctx) {
    const int n = blockIdx.x;
    const int tid = threadIdx.x;  // 256
    __shared__ float a[SDIM];
    __shared__ float rmax[4], rsum[4];

    float v = 0.f, e = 0.f;
    if (tid < SDIM) {
        const int idx = tid * BATCH + n;
        v = part[idx] + part[NSCORE + idx] + part[2 * NSCORE + idx] +
            part[3 * NSCORE + idx];
        float m = warp_max(v);
        if ((tid & 31) == 0) rmax[tid >> 5] = m;
    }
    __syncthreads();
    if (tid < SDIM) {
        float m = fmaxf(fmaxf(rmax[0], rmax[1]), fmaxf(rmax[2], rmax[3]));
        e = expf(v - m);
        float s = warp_sum(e);
        if ((tid & 31) == 0) rsum[tid >> 5] = s;
    }
    __syncthreads();
    if (tid < SDIM) {
        float sum = rsum[0] + rsum[1] + rsum[2] + rsum[3];
        float av = e / sum;
        attn_out[tid * BATCH + n] = av;
        a[tid] = av;
    }
    __syncthreads();

    float4 acc = make_float4(0.f, 0.f, 0.f, 0.f);
    for (int s = 0; s < SDIM; s++) {
        const __half2* ep =
            (const __half2*)(encH + ((size_t)s * BATCH + n) * HDIM) + tid * 2;
        float2 f0 = __half22float2(ep[0]);
        float2 f1 = __half22float2(ep[1]);
        float w = a[s];
        acc.x = fmaf(w, f0.x, acc.x);
        acc.y = fmaf(w, f0.y, acc.y);
        acc.z = fmaf(w, f1.x, acc.z);
        acc.w = fmaf(w, f1.y, acc.w);
    }
    ((float4*)(ctx + (size_t)n * HDIM))[tid] = acc;
}

// ---------------- GRU combine + LayerNorm ----------------
__global__ void fuse_hln_kernel(const float* __restrict__ gates,
                                const float* __restrict__ t1,
                                const float* __restrict__ t2,
                                const float* __restrict__ hid,
                                const float* __restrict__ lng,
                                const float* __restrict__ lnb,
                                float* __restrict__ hout) {
    const int n = blockIdx.x;
    const int tid = threadIdx.x;  // 256
    float4 z = ((const float4*)(gates + (size_t)n * 2 * HDIM))[tid];
    float4 r = ((const float4*)(gates + (size_t)n * 2 * HDIM + HDIM))[tid];
    float4 a = ((const float4*)(t1 + (size_t)n * HDIM))[tid];
    float4 b = ((const float4*)(t2 + (size_t)n * HDIM))[tid];
    float4 hv = ((const float4*)(hid + (size_t)n * HDIM))[tid];
    float4 hr;
    hr.x = (1.0f - z.x) * hv.x + z.x * tanhf(a.x + r.x * b.x);
    hr.y = (1.0f - z.y) * hv.y + z.y * tanhf(a.y + r.y * b.y);
    hr.z = (1.0f - z.z) * hv.z + z.z * tanhf(a.z + r.z * b.z);
    hr.w = (1.0f - z.w) * hv.w + z.w * tanhf(a.w + r.w * b.w);
    float s = hr.x + hr.y + hr.z + hr.w;
    float ss = hr.x * hr.x + hr.y * hr.y + hr.z * hr.z + hr.w * hr.w;
    __shared__ float sm1[8], sm2[8];
    float w1 = warp_sum(s), w2 = warp_sum(ss);
    if ((tid & 31) == 0) { sm1[tid >> 5] = w1; sm2[tid >> 5] = w2; }
    __syncthreads();
    float tot1 = 0.f, tot2 = 0.f;
#pragma unroll
    for (int qq = 0; qq < 8; qq++) { tot1 += sm1[qq]; tot2 += sm2[qq]; }
    float mu = tot1 * (1.0f / HDIM);
    float var = tot2 * (1.0f / HDIM) - mu * mu;
    float inv = rsqrtf(var + 1e-5f);
    float4 gg = ((const float4*)lng)[tid];
    float4 bb = ((const float4*)lnb)[tid];
    float4 o;
    o.x = (hr.x - mu) * inv * gg.x + bb.x;
    o.y = (hr.y - mu) * inv * gg.y + bb.y;
    o.z = (hr.z - mu) * inv * gg.z + bb.z;
    o.w = (hr.w - mu) * inv * gg.w + bb.w;
    ((float4*)(hout + (size_t)n * HDIM))[tid] = o;
}

// ---------------- final log_softmax: reduce partials + single RW pass ---------
__global__ void logsoftmax2_kernel(float* __restrict__ logits,
                                   const float* __restrict__ lmax,
                                   const float* __restrict__ lsum) {
    const int n = blockIdx.x;
    const int tid = threadIdx.x;  // 512
    __shared__ float sm[16];

    float m = -3.4e38f;
    for (int i = tid; i < NB2; i += 512) m = fmaxf(m, lmax[(size_t)i * BATCH + n]);
    m = warp_max(m);
    if ((tid & 31) == 0) sm[tid >> 5] = m;
    __syncthreads();
    float gmax = -3.4e38f;
#pragma unroll
    for (int qq = 0; qq < 16; qq++) gmax = fmaxf(gmax, sm[qq]);
    __syncthreads();

    float s = 0.f;
    for (int i = tid; i < NB2; i += 512)
        s += lsum[(size_t)i * BATCH + n] * expf(lmax[(size_t)i * BATCH + n] - gmax);
    s = warp_sum(s);
    if ((tid & 31) == 0) sm[tid >> 5] = s;
    __syncthreads();
    float tot = 0.f;
#pragma unroll
    for (int qq = 0; qq < 16; qq++) tot += sm[qq];
    float lse = gmax + logf(tot);

    float* row = logits + (size_t)n * VDIM;
    for (int i = tid; i < VDIM; i += 512) row[i] -= lse;
}

// ---------------- launch ----------------
extern "C" void kernel_launch(void* const* d_in, const int* in_sizes, int n_in,
                              void* d_out, int out_size) {
    const int* ids = (const int*)d_in[0];
    const float* hidden = (const float*)d_in[1];
    const float* enc = (const float*)d_in[2];
    const float* emb = (const float*)d_in[3];
    const float* W_w = (const float*)d_in[4];
    const float* W_b = (const float*)d_in[5];
    const float* U_w = (const float*)d_in[6];
    const float* U_b = (const float*)d_in[7];
    const float* v_w = (const float*)d_in[8];
    // d_in[9] = v_b : constant over S, cancels in softmax
    const float* ih_w = (const float*)d_in[10];
    const float* ih_b = (const float*)d_in[11];
    const float* hh_w = (const float*)d_in[12];
    const float* hh_b = (const float*)d_in[13];
    const float* cand_w = (const float*)d_in[14];
    const float* cand_b = (const float*)d_in[15];
    const float* hhc_w = (const float*)d_in[16];
    const float* hhc_b = (const float*)d_in[17];
    const float* comb_w = (const float*)d_in[18];
    const float* comb_b = (const float*)d_in[19];
    const float* ln_g = (const float*)d_in[20];
    const float* ln_b = (const float*)d_in[21];
    const float* out1_w = (const float*)d_in[22];
    const float* out1_b = (const float*)d_in[23];
    const float* out2_w = (const float*)d_in[24];
    const float* out2_b = (const float*)d_in[25];

    float* out_logits = (float*)d_out;
    float* out_h = out_logits + (size_t)BATCH * VDIM;
    float* out_attn = out_h + (size_t)BATCH * HDIM;

    float *Wh, *score4, *ctx, *gbuf, *gates, *t1, *t2, *lmax, *lsum;
    __half *encH, *o1h;
    uint32_t* UwP;
    cudaGetSymbolAddress((void**)&Wh, g_Wh);
    cudaGetSymbolAddress((void**)&score4, g_score4);
    cudaGetSymbolAddress((void**)&ctx, g_ctx);
    cudaGetSymbolAddress((void**)&gbuf, g_g);
    cudaGetSymbolAddress((void**)&gates, g_gates);
    cudaGetSymbolAddress((void**)&t1, g_t1);
    cudaGetSymbolAddress((void**)&t2, g_t2);
    cudaGetSymbolAddress((void**)&encH, g_encH);
    cudaGetSymbolAddress((void**)&o1h, g_o1h);
    cudaGetSymbolAddress((void**)&UwP, g_UwP);
    cudaGetSymbolAddress((void**)&lmax, g_lmax);
    cudaGetSymbolAddress((void**)&lsum, g_lsum);

    cudaFuncSetAttribute(score_gemm, cudaFuncAttributeMaxDynamicSharedMemorySize,
                         SMEMH);
    cudaFuncSetAttribute(out2_gemm, cudaFuncAttributeMaxDynamicSharedMemorySize,
                         SMEMO);
    cudaFuncSetAttribute(tgemm64<Plain64>,
                         cudaFuncAttributeMaxDynamicSharedMemorySize, SM64);
    cudaFuncSetAttribute(tgemm64<Plain64H>,
                         cudaFuncAttributeMaxDynamicSharedMemorySize, SM64);
    cudaFuncSetAttribute(tgemm64<Comb64>,
                         cudaFuncAttributeMaxDynamicSharedMemorySize, SM64);
    cudaFuncSetAttribute(tgemm64<Fused3_64>,
                         cudaFuncAttributeMaxDynamicSharedMemorySize, SM64);

    // 0. conversions
    f2h_kernel<<<(SDIM * BATCH * HDIM) / 1024, 256>>>(enc, encH, SDIM * BATCH * HDIM);
    packb_kernel<<<dim3(HDIM / 256, HDIM / 2), 256>>>(U_w, UwP, HDIM, HDIM);

    // 1. Wh = hidden @ W_w + W_b
    {
        Plain64 p{hidden, W_w, W_b, Wh, HDIM, HDIM, 0};
        tgemm64<Plain64><<<dim3(HDIM / 64, BATCH / 64), 128, SM64>>>(p);
    }
    // 2. fused score GEMM (512 threads, ldmatrix A) -> 4 partial buffers
    score_gemm<<<dim3(HDIM / 256, (SDIM * BATCH) / 128), 512, SMEMH>>>(
        encH, UwP, Wh, U_b, v_w, score4);
    // 3. fused softmax + context (fp16 enc)
    softmax_ctx_kernel<<<BATCH, 256>>>(score4, encH, out_attn, ctx);
    // 4. g = relu([emb[ids], ctx] @ comb_w + comb_b)
    {
        Comb64 p{emb, ids, ctx, comb_w, comb_b, gbuf, EDIM + HDIM};
        tgemm64<Comb64><<<dim3(EDIM / 64, BATCH / 64), 128, SM64>>>(p);
    }
    // 5. fused gates | t1 | t2
    {
        Fused3_64 p{gbuf, hidden, ih_w, hh_w, cand_w, hhc_w,
                    ih_b, hh_b, cand_b, hhc_b, gates, t1, t2, EDIM + HDIM};
        tgemm64<Fused3_64><<<dim3(4096 / 64, BATCH / 64), 128, SM64>>>(p);
    }
    // 6. GRU combine + LayerNorm
    fuse_hln_kernel<<<BATCH, 256>>>(gates, t1, t2, hidden, ln_g, ln_b, out_h);
    // 7. o1h = relu(h @ out1_w + out1_b) directly in fp16
    {
        Plain64H p{out_h, out1_w, out1_b, o1h, HDIM, HDIM};
        tgemm64<Plain64H><<<dim3(HDIM / 64, BATCH / 64), 128, SM64>>>(p);
    }
    // 8. logits + fused log-softmax partials (512 threads, ldmatrix A)
    out2_gemm<<<dim3(BATCH / 128, NB2), 512, SMEMO>>>(o1h, out2_w, out2_b, out_logits,
                                                      lmax, lsum);
    // 9. final log_softmax: reduce partials + single pass
    logsoftmax2_kernel<<<BATCH, 512>>>(out_logits, lmax, lsum);
}